// round 4
// baseline (speedup 1.0000x reference)
#include <cuda_runtime.h>
#include <math.h>

#define NN 100000
#define EE 1600000
#define DIN 256
#define DH 64
#define DOUT 3
#define NG 64
#define BN_EPSF 1e-5f

// ---------------- scratch (device globals; no allocation allowed) -------------
__device__ int    d_deg[NN];
__device__ float  d_dinv[NN];
__device__ int    d_rowoff[NN + 1];
__device__ int    d_fillpos[NN];
__device__ int    d_csrc[EE];
__device__ float  d_cw[EE];
__device__ __align__(16) float d_bufT[(size_t)NN * DH];   // transformed features
__device__ __align__(16) float d_bufA[(size_t)NN * DH];   // aggregated / activated
__device__ __align__(16) float d_h3t[NN * DOUT + 4];
__device__ __align__(16) float d_h3[NN * DOUT + 4];
__device__ float  d_sum1[DH], d_sq1[DH], d_sum2[DH], d_sq2[DH];
__device__ float  d_pool[NG * 4];

// ---------------- structure build ---------------------------------------------
__global__ void k_init() {
    int i = blockIdx.x * blockDim.x + threadIdx.x;
    if (i < NN) d_deg[i] = 1;                       // self-loop contributes 1
    if (i < DH) { d_sum1[i] = 0.f; d_sq1[i] = 0.f; d_sum2[i] = 0.f; d_sq2[i] = 0.f; }
    if (i < NG * 4) d_pool[i] = 0.f;
}

__global__ void k_hist(const int* __restrict__ ei) {
    int e = blockIdx.x * blockDim.x + threadIdx.x;
    if (e < EE) atomicAdd(&d_deg[ei[EE + e]], 1);
}

__global__ void k_dinv() {
    int i = blockIdx.x * blockDim.x + threadIdx.x;
    if (i < NN) d_dinv[i] = rsqrtf((float)d_deg[i]);
}

// single-block exclusive scan of (deg-1) -> row offsets (and fill cursor copy)
__global__ void k_scan() {
    const int T = 1024;
    __shared__ int part[T];
    int t = threadIdx.x;
    const int chunk = (NN + T - 1) / T;
    int b = t * chunk;
    int e = min(b + chunk, NN);
    int s = 0;
    for (int i = b; i < e; i++) s += d_deg[i] - 1;
    part[t] = s;
    __syncthreads();
    for (int off = 1; off < T; off <<= 1) {
        int add = (t >= off) ? part[t - off] : 0;
        __syncthreads();
        part[t] += add;
        __syncthreads();
    }
    int run = (t > 0) ? part[t - 1] : 0;
    for (int i = b; i < e; i++) {
        d_rowoff[i] = run;
        d_fillpos[i] = run;
        run += d_deg[i] - 1;
    }
    if (t == T - 1) d_rowoff[NN] = part[T - 1];
}

__global__ void k_fill(const int* __restrict__ ei) {
    int e = blockIdx.x * blockDim.x + threadIdx.x;
    if (e >= EE) return;
    int s = ei[e];
    int d = ei[EE + e];
    int p = atomicAdd(&d_fillpos[d], 1);
    d_csrc[p] = s;
    d_cw[p] = d_dinv[s] * d_dinv[d];
}

// ---------------- GEMM: [nrows,K] @ [K,64] -> [nrows,64] -----------------------
template <int K>
__global__ void k_gemm64(const float* __restrict__ A, const float* __restrict__ W,
                         float* __restrict__ out, int nrows)
{
    __shared__ float sA[16 * 64];   // sA[k][r]  (A transposed in smem)
    __shared__ float sB[16 * 64];   // sB[k][c]
    int tid = threadIdx.x;
    int tx = tid & 15;              // col group
    int ty = tid >> 4;              // row group
    int row0 = blockIdx.x * 64;

    float acc[4][4];
#pragma unroll
    for (int i = 0; i < 4; i++)
#pragma unroll
        for (int j = 0; j < 4; j++) acc[i][j] = 0.f;

    int ar = tid >> 2;              // 0..63
    int ak = (tid & 3) * 4;         // 0,4,8,12
    int bk = tid >> 4;              // 0..15
    int bc = (tid & 15) * 4;        // 0..60

    for (int k0 = 0; k0 < K; k0 += 16) {
        float4 av = make_float4(0.f, 0.f, 0.f, 0.f);
        int arow = row0 + ar;
        if (arow < nrows)
            av = *(const float4*)(A + (size_t)arow * K + k0 + ak);
        sA[(ak + 0) * 64 + ar] = av.x;
        sA[(ak + 1) * 64 + ar] = av.y;
        sA[(ak + 2) * 64 + ar] = av.z;
        sA[(ak + 3) * 64 + ar] = av.w;
        float4 bv = *(const float4*)(W + (size_t)(k0 + bk) * 64 + bc);
        *(float4*)(sB + bk * 64 + bc) = bv;
        __syncthreads();
#pragma unroll
        for (int k = 0; k < 16; k++) {
            float a0 = sA[k * 64 + ty * 4 + 0];
            float a1 = sA[k * 64 + ty * 4 + 1];
            float a2 = sA[k * 64 + ty * 4 + 2];
            float a3 = sA[k * 64 + ty * 4 + 3];
            float b0 = sB[k * 64 + tx * 4 + 0];
            float b1 = sB[k * 64 + tx * 4 + 1];
            float b2 = sB[k * 64 + tx * 4 + 2];
            float b3 = sB[k * 64 + tx * 4 + 3];
            acc[0][0] = fmaf(a0, b0, acc[0][0]); acc[0][1] = fmaf(a0, b1, acc[0][1]);
            acc[0][2] = fmaf(a0, b2, acc[0][2]); acc[0][3] = fmaf(a0, b3, acc[0][3]);
            acc[1][0] = fmaf(a1, b0, acc[1][0]); acc[1][1] = fmaf(a1, b1, acc[1][1]);
            acc[1][2] = fmaf(a1, b2, acc[1][2]); acc[1][3] = fmaf(a1, b3, acc[1][3]);
            acc[2][0] = fmaf(a2, b0, acc[2][0]); acc[2][1] = fmaf(a2, b1, acc[2][1]);
            acc[2][2] = fmaf(a2, b2, acc[2][2]); acc[2][3] = fmaf(a2, b3, acc[2][3]);
            acc[3][0] = fmaf(a3, b0, acc[3][0]); acc[3][1] = fmaf(a3, b1, acc[3][1]);
            acc[3][2] = fmaf(a3, b2, acc[3][2]); acc[3][3] = fmaf(a3, b3, acc[3][3]);
        }
        __syncthreads();
    }
#pragma unroll
    for (int i = 0; i < 4; i++) {
        int r = row0 + ty * 4 + i;
        if (r < nrows) {
            float4 v = make_float4(acc[i][0], acc[i][1], acc[i][2], acc[i][3]);
            *(float4*)(out + (size_t)r * 64 + tx * 4) = v;
        }
    }
}

// ---------------- aggregation (pull, CSR by dst), C=64: warp per node ----------
__global__ void k_agg64(const float* __restrict__ ht, const float* __restrict__ bias,
                        float* __restrict__ out)
{
    int warp = (blockIdx.x * blockDim.x + threadIdx.x) >> 5;
    int lane = threadIdx.x & 31;
    if (warp >= NN) return;
    const int i = warp;
    float di = d_dinv[i];
    float ws = di * di;                       // self-loop weight
    float acc0 = ws * ht[i * 64 + lane];
    float acc1 = ws * ht[i * 64 + 32 + lane];
    int e0 = d_rowoff[i], e1 = d_rowoff[i + 1];
    for (int j0 = e0; j0 < e1; j0 += 32) {
        int j = j0 + lane;
        int src = 0; float w = 0.f;
        if (j < e1) { src = d_csrc[j]; w = d_cw[j]; }
        int cnt = min(32, e1 - j0);
#pragma unroll 4
        for (int k = 0; k < cnt; k++) {
            int   sk = __shfl_sync(0xffffffffu, src, k);
            float wk = __shfl_sync(0xffffffffu, w, k);
            acc0 = fmaf(wk, __ldg(&ht[sk * 64 + lane]),      acc0);
            acc1 = fmaf(wk, __ldg(&ht[sk * 64 + 32 + lane]), acc1);
        }
    }
    out[i * 64 + lane]      = acc0 + bias[lane];
    out[i * 64 + 32 + lane] = acc1 + bias[32 + lane];
}

// ---------------- batchnorm stats / apply --------------------------------------
__global__ void k_stats(const float* __restrict__ h, float* __restrict__ sum,
                        float* __restrict__ sq)
{
    int c = threadIdx.x & 63;
    int r = threadIdx.x >> 6;                 // 0..3
    float s = 0.f, q = 0.f;
    for (int i = blockIdx.x * 4 + r; i < NN; i += gridDim.x * 4) {
        float v = h[i * 64 + c];
        s += v;
        q = fmaf(v, v, q);
    }
    __shared__ float ss[256], qq[256];
    ss[threadIdx.x] = s; qq[threadIdx.x] = q;
    __syncthreads();
    if (r == 0) {
        s = ss[c] + ss[64 + c] + ss[128 + c] + ss[192 + c];
        q = qq[c] + qq[64 + c] + qq[128 + c] + qq[192 + c];
        atomicAdd(&sum[c], s);
        atomicAdd(&sq[c], q);
    }
}

__global__ void k_bnrelu(float* __restrict__ h, const float* __restrict__ g,
                         const float* __restrict__ be, const float* __restrict__ sum,
                         const float* __restrict__ sq)
{
    int idx = blockIdx.x * blockDim.x + threadIdx.x;
    if (idx >= NN * DH) return;
    int c = idx & 63;
    float mu  = sum[c] * (1.0f / NN);
    float var = sq[c] * (1.0f / NN) - mu * mu;
    float v = fmaf((h[idx] - mu) * rsqrtf(var + BN_EPSF), g[c], be[c]);
    h[idx] = fmaxf(v, 0.f);
}

// ---------------- layer 3: [N,64]@[64,3], then C=3 aggregation -----------------
__global__ void k_gemm3(const float* __restrict__ h, const float* __restrict__ W3,
                        float* __restrict__ out)
{
    __shared__ float w[DH * DOUT];
    if (threadIdx.x < DH * DOUT) w[threadIdx.x] = W3[threadIdx.x];
    __syncthreads();
    int i = blockIdx.x * blockDim.x + threadIdx.x;
    if (i >= NN) return;
    float a0 = 0.f, a1 = 0.f, a2 = 0.f;
    const float4* hp = (const float4*)(h + (size_t)i * DH);
#pragma unroll
    for (int q4 = 0; q4 < 16; q4++) {
        float4 v = hp[q4];
        int k = q4 * 4;
        a0 = fmaf(v.x, w[(k + 0) * 3 + 0], a0); a1 = fmaf(v.x, w[(k + 0) * 3 + 1], a1); a2 = fmaf(v.x, w[(k + 0) * 3 + 2], a2);
        a0 = fmaf(v.y, w[(k + 1) * 3 + 0], a0); a1 = fmaf(v.y, w[(k + 1) * 3 + 1], a1); a2 = fmaf(v.y, w[(k + 1) * 3 + 2], a2);
        a0 = fmaf(v.z, w[(k + 2) * 3 + 0], a0); a1 = fmaf(v.z, w[(k + 2) * 3 + 1], a1); a2 = fmaf(v.z, w[(k + 2) * 3 + 2], a2);
        a0 = fmaf(v.w, w[(k + 3) * 3 + 0], a0); a1 = fmaf(v.w, w[(k + 3) * 3 + 1], a1); a2 = fmaf(v.w, w[(k + 3) * 3 + 2], a2);
    }
    out[i * 3 + 0] = a0; out[i * 3 + 1] = a1; out[i * 3 + 2] = a2;
}

__global__ void k_agg3(const float* __restrict__ ht, const float* __restrict__ b3,
                       float* __restrict__ out)
{
    int i = blockIdx.x * blockDim.x + threadIdx.x;
    if (i >= NN) return;
    float di = d_dinv[i], ws = di * di;
    float a0 = ws * ht[i * 3 + 0];
    float a1 = ws * ht[i * 3 + 1];
    float a2 = ws * ht[i * 3 + 2];
    int e1 = d_rowoff[i + 1];
    for (int j = d_rowoff[i]; j < e1; j++) {
        int s = d_csrc[j];
        float w = d_cw[j];
        a0 = fmaf(w, ht[s * 3 + 0], a0);
        a1 = fmaf(w, ht[s * 3 + 1], a1);
        a2 = fmaf(w, ht[s * 3 + 2], a2);
    }
    out[i * 3 + 0] = a0 + b3[0];
    out[i * 3 + 1] = a1 + b3[1];
    out[i * 3 + 2] = a2 + b3[2];
}

// ---------------- pooling + log_softmax ----------------------------------------
__global__ void k_pool(const float* __restrict__ h3, const int* __restrict__ batch)
{
    __shared__ float sh[NG * 4];
    if (threadIdx.x < NG * 4) sh[threadIdx.x] = 0.f;
    __syncthreads();
    int i = blockIdx.x * blockDim.x + threadIdx.x;
    if (i < NN) {
        int g = batch[i];
        atomicAdd(&sh[g * 4 + 0], h3[i * 3 + 0]);
        atomicAdd(&sh[g * 4 + 1], h3[i * 3 + 1]);
        atomicAdd(&sh[g * 4 + 2], h3[i * 3 + 2]);
        atomicAdd(&sh[g * 4 + 3], 1.0f);
    }
    __syncthreads();
    if (threadIdx.x < NG * 4 && sh[threadIdx.x] != 0.f)
        atomicAdd(&d_pool[threadIdx.x], sh[threadIdx.x]);
}

__global__ void k_final(float* __restrict__ out)
{
    int g = threadIdx.x;
    if (g >= NG) return;
    float cnt = fmaxf(d_pool[g * 4 + 3], 1.0f);
    float v0 = d_pool[g * 4 + 0] / cnt;
    float v1 = d_pool[g * 4 + 1] / cnt;
    float v2 = d_pool[g * 4 + 2] / cnt;
    float m = fmaxf(v0, fmaxf(v1, v2));
    float l = m + logf(expf(v0 - m) + expf(v1 - m) + expf(v2 - m));
    out[g * 3 + 0] = v0 - l;
    out[g * 3 + 1] = v1 - l;
    out[g * 3 + 2] = v2 - l;
}

// ---------------- launch --------------------------------------------------------
extern "C" void kernel_launch(void* const* d_in, const int* in_sizes, int n_in,
                              void* d_out, int out_size)
{
    const float* x    = (const float*)d_in[0];
    const int*   ei   = (const int*)d_in[1];
    const int*   batch= (const int*)d_in[2];
    const float* W1   = (const float*)d_in[3];
    const float* b1   = (const float*)d_in[4];
    const float* g1   = (const float*)d_in[5];
    const float* be1  = (const float*)d_in[6];
    const float* W2   = (const float*)d_in[7];
    const float* b2   = (const float*)d_in[8];
    const float* g2   = (const float*)d_in[9];
    const float* be2  = (const float*)d_in[10];
    const float* W3   = (const float*)d_in[11];
    const float* b3   = (const float*)d_in[12];
    float* out = (float*)d_out;

    float *bufT, *bufA, *h3t, *h3, *sum1, *sq1, *sum2, *sq2;
    cudaGetSymbolAddress((void**)&bufT, d_bufT);
    cudaGetSymbolAddress((void**)&bufA, d_bufA);
    cudaGetSymbolAddress((void**)&h3t,  d_h3t);
    cudaGetSymbolAddress((void**)&h3,   d_h3);
    cudaGetSymbolAddress((void**)&sum1, d_sum1);
    cudaGetSymbolAddress((void**)&sq1,  d_sq1);
    cudaGetSymbolAddress((void**)&sum2, d_sum2);
    cudaGetSymbolAddress((void**)&sq2,  d_sq2);

    const int TB = 256;
    int gN = (NN + TB - 1) / TB;
    int gE = (EE + TB - 1) / TB;

    // structure
    k_init<<<gN, TB>>>();
    k_hist<<<gE, TB>>>(ei);
    k_dinv<<<gN, TB>>>();
    k_scan<<<1, 1024>>>();
    k_fill<<<gE, TB>>>(ei);

    // layer 1
    k_gemm64<DIN><<<(NN + 63) / 64, 256>>>(x, W1, bufT, NN);
    k_agg64<<<(NN * 32 + TB - 1) / TB, TB>>>(bufT, b1, bufA);
    k_stats<<<128, 256>>>(bufA, sum1, sq1);
    k_bnrelu<<<(NN * DH + TB - 1) / TB, TB>>>(bufA, g1, be1, sum1, sq1);

    // layer 2
    k_gemm64<DH><<<(NN + 63) / 64, 256>>>(bufA, W2, bufT, NN);
    k_agg64<<<(NN * 32 + TB - 1) / TB, TB>>>(bufT, b2, bufA);
    k_stats<<<128, 256>>>(bufA, sum2, sq2);
    k_bnrelu<<<(NN * DH + TB - 1) / TB, TB>>>(bufA, g2, be2, sum2, sq2);

    // layer 3 + pooling + log_softmax
    k_gemm3<<<gN, TB>>>(bufA, W3, h3t);
    k_agg3<<<gN, TB>>>(h3t, b3, h3);
    k_pool<<<gN, TB>>>(h3, batch);
    k_final<<<1, 64>>>(out);
}

// round 5
// speedup vs baseline: 1.3433x; 1.3433x over previous
#include <cuda_runtime.h>
#include <math.h>

#define NN 100000
#define EE 1600000
#define DIN 256
#define DH 64
#define DOUT 3
#define NG 64
#define BN_EPSF 1e-5f

#define SCAN_ELEMS 1024                       // elements per scan block (256 thr * 4)
#define NBLK ((NN + SCAN_ELEMS - 1) / SCAN_ELEMS)   // 98

// ---------------- scratch (device globals; no allocation allowed) -------------
__device__ int    d_deg[NN];
__device__ __align__(16) float d_dinv[NN];
__device__ int    d_rowoff[NN + 1];
__device__ int    d_fillpos[NN];
__device__ int    d_blocksum[NBLK];
__device__ int    d_blockoff[NBLK];
__device__ int    d_csrc[EE];
__device__ float  d_cw[EE];
__device__ __align__(16) float d_bufT[(size_t)NN * DH];   // transformed features
__device__ __align__(16) float d_bufA[(size_t)NN * DH];   // aggregated / activated
__device__ __align__(16) float d_h3t[NN * DOUT + 4];
__device__ __align__(16) float d_h3[NN * DOUT + 4];
__device__ float  d_sum1[DH], d_sq1[DH], d_sum2[DH], d_sq2[DH];
__device__ float  d_pool[NG * 4];

// ---------------- structure build ---------------------------------------------
__global__ void k_init() {
    int i = blockIdx.x * blockDim.x + threadIdx.x;
    if (i < NN) d_deg[i] = 1;                       // self-loop contributes 1
    if (i < DH) { d_sum1[i] = 0.f; d_sq1[i] = 0.f; d_sum2[i] = 0.f; d_sq2[i] = 0.f; }
    if (i < NG * 4) d_pool[i] = 0.f;
}

__global__ void k_hist(const int* __restrict__ ei) {
    int e = blockIdx.x * blockDim.x + threadIdx.x;
    if (e < EE) atomicAdd(&d_deg[ei[EE + e]], 1);
}

// phase 1: per-block sums of (deg-1), fused with dinv = rsqrt(deg)
// NN % 4 == 0, so an int4 at idx is fully in-range iff idx < NN.
__global__ void k_partial() {
    int t = threadIdx.x;
    int idx = blockIdx.x * SCAN_ELEMS + t * 4;
    int s = 0;
    if (idx < NN) {
        int4 d = *(const int4*)(d_deg + idx);
        s = d.x + d.y + d.z + d.w - 4;
        float4 r;
        r.x = rsqrtf((float)d.x);
        r.y = rsqrtf((float)d.y);
        r.z = rsqrtf((float)d.z);
        r.w = rsqrtf((float)d.w);
        *(float4*)(d_dinv + idx) = r;
    }
    __shared__ int sh[8];
#pragma unroll
    for (int o = 16; o; o >>= 1) s += __shfl_down_sync(0xffffffffu, s, o);
    if ((t & 31) == 0) sh[t >> 5] = s;
    __syncthreads();
    if (t < 32) {
        int v = (t < 8) ? sh[t] : 0;
#pragma unroll
        for (int o = 4; o; o >>= 1) v += __shfl_down_sync(0xffffffffu, v, o);
        if (t == 0) d_blocksum[blockIdx.x] = v;
    }
}

// phase 2: exclusive scan of NBLK block sums (single small block)
__global__ void k_scanblock() {
    __shared__ int sh[128];
    int t = threadIdx.x;
    int v = (t < NBLK) ? d_blocksum[t] : 0;
    sh[t] = v;
    __syncthreads();
#pragma unroll
    for (int off = 1; off < 128; off <<= 1) {
        int a = (t >= off) ? sh[t - off] : 0;
        __syncthreads();
        sh[t] += a;
        __syncthreads();
    }
    if (t < NBLK) d_blockoff[t] = sh[t] - v;     // exclusive
    if (t == 127) d_rowoff[NN] = sh[127];        // total = EE
}

// phase 3: write row offsets + fill cursors
__global__ void k_scatter() {
    __shared__ int tsum[256];
    int t = threadIdx.x;
    int idx = blockIdx.x * SCAN_ELEMS + t * 4;
    int v0 = 0, v1 = 0, v2 = 0, v3 = 0;
    if (idx < NN) {
        int4 d = *(const int4*)(d_deg + idx);
        v0 = d.x - 1; v1 = d.y - 1; v2 = d.z - 1; v3 = d.w - 1;
    }
    int s = v0 + v1 + v2 + v3;
    tsum[t] = s;
    __syncthreads();
#pragma unroll
    for (int off = 1; off < 256; off <<= 1) {
        int a = (t >= off) ? tsum[t - off] : 0;
        __syncthreads();
        tsum[t] += a;
        __syncthreads();
    }
    if (idx < NN) {
        int run = d_blockoff[blockIdx.x] + tsum[t] - s;   // exclusive within block
        int4 ro = make_int4(run, run + v0, run + v0 + v1, run + v0 + v1 + v2);
        *(int4*)(d_rowoff  + idx) = ro;
        *(int4*)(d_fillpos + idx) = ro;
    }
}

__global__ void k_fill(const int* __restrict__ ei) {
    int e = blockIdx.x * blockDim.x + threadIdx.x;
    if (e >= EE) return;
    int s = ei[e];
    int d = ei[EE + e];
    int p = atomicAdd(&d_fillpos[d], 1);
    d_csrc[p] = s;
    d_cw[p] = d_dinv[s] * d_dinv[d];
}

// ---------------- GEMM: [nrows,K] @ [K,64] -> [nrows,64] -----------------------
template <int K>
__global__ void k_gemm64(const float* __restrict__ A, const float* __restrict__ W,
                         float* __restrict__ out, int nrows)
{
    __shared__ float sA[16 * 64];   // sA[k][r]  (A transposed in smem)
    __shared__ float sB[16 * 64];   // sB[k][c]
    int tid = threadIdx.x;
    int tx = tid & 15;              // col group
    int ty = tid >> 4;              // row group
    int row0 = blockIdx.x * 64;

    float acc[4][4];
#pragma unroll
    for (int i = 0; i < 4; i++)
#pragma unroll
        for (int j = 0; j < 4; j++) acc[i][j] = 0.f;

    int ar = tid >> 2;              // 0..63
    int ak = (tid & 3) * 4;         // 0,4,8,12
    int bk = tid >> 4;              // 0..15
    int bc = (tid & 15) * 4;        // 0..60

    for (int k0 = 0; k0 < K; k0 += 16) {
        float4 av = make_float4(0.f, 0.f, 0.f, 0.f);
        int arow = row0 + ar;
        if (arow < nrows)
            av = *(const float4*)(A + (size_t)arow * K + k0 + ak);
        sA[(ak + 0) * 64 + ar] = av.x;
        sA[(ak + 1) * 64 + ar] = av.y;
        sA[(ak + 2) * 64 + ar] = av.z;
        sA[(ak + 3) * 64 + ar] = av.w;
        float4 bv = *(const float4*)(W + (size_t)(k0 + bk) * 64 + bc);
        *(float4*)(sB + bk * 64 + bc) = bv;
        __syncthreads();
#pragma unroll
        for (int k = 0; k < 16; k++) {
            float a0 = sA[k * 64 + ty * 4 + 0];
            float a1 = sA[k * 64 + ty * 4 + 1];
            float a2 = sA[k * 64 + ty * 4 + 2];
            float a3 = sA[k * 64 + ty * 4 + 3];
            float b0 = sB[k * 64 + tx * 4 + 0];
            float b1 = sB[k * 64 + tx * 4 + 1];
            float b2 = sB[k * 64 + tx * 4 + 2];
            float b3 = sB[k * 64 + tx * 4 + 3];
            acc[0][0] = fmaf(a0, b0, acc[0][0]); acc[0][1] = fmaf(a0, b1, acc[0][1]);
            acc[0][2] = fmaf(a0, b2, acc[0][2]); acc[0][3] = fmaf(a0, b3, acc[0][3]);
            acc[1][0] = fmaf(a1, b0, acc[1][0]); acc[1][1] = fmaf(a1, b1, acc[1][1]);
            acc[1][2] = fmaf(a1, b2, acc[1][2]); acc[1][3] = fmaf(a1, b3, acc[1][3]);
            acc[2][0] = fmaf(a2, b0, acc[2][0]); acc[2][1] = fmaf(a2, b1, acc[2][1]);
            acc[2][2] = fmaf(a2, b2, acc[2][2]); acc[2][3] = fmaf(a2, b3, acc[2][3]);
            acc[3][0] = fmaf(a3, b0, acc[3][0]); acc[3][1] = fmaf(a3, b1, acc[3][1]);
            acc[3][2] = fmaf(a3, b2, acc[3][2]); acc[3][3] = fmaf(a3, b3, acc[3][3]);
        }
        __syncthreads();
    }
#pragma unroll
    for (int i = 0; i < 4; i++) {
        int r = row0 + ty * 4 + i;
        if (r < nrows) {
            float4 v = make_float4(acc[i][0], acc[i][1], acc[i][2], acc[i][3]);
            *(float4*)(out + (size_t)r * 64 + tx * 4) = v;
        }
    }
}

// ---------------- aggregation (pull, CSR by dst), C=64: warp per node ----------
__global__ void k_agg64(const float* __restrict__ ht, const float* __restrict__ bias,
                        float* __restrict__ out)
{
    int warp = (blockIdx.x * blockDim.x + threadIdx.x) >> 5;
    int lane = threadIdx.x & 31;
    if (warp >= NN) return;
    const int i = warp;
    float di = d_dinv[i];
    float ws = di * di;                       // self-loop weight
    float acc0 = ws * ht[i * 64 + lane];
    float acc1 = ws * ht[i * 64 + 32 + lane];
    int e0 = d_rowoff[i], e1 = d_rowoff[i + 1];
    for (int j0 = e0; j0 < e1; j0 += 32) {
        int j = j0 + lane;
        int src = 0; float w = 0.f;
        if (j < e1) { src = d_csrc[j]; w = d_cw[j]; }
        int cnt = min(32, e1 - j0);
#pragma unroll 4
        for (int k = 0; k < cnt; k++) {
            int   sk = __shfl_sync(0xffffffffu, src, k);
            float wk = __shfl_sync(0xffffffffu, w, k);
            acc0 = fmaf(wk, __ldg(&ht[sk * 64 + lane]),      acc0);
            acc1 = fmaf(wk, __ldg(&ht[sk * 64 + 32 + lane]), acc1);
        }
    }
    out[i * 64 + lane]      = acc0 + bias[lane];
    out[i * 64 + 32 + lane] = acc1 + bias[32 + lane];
}

// ---------------- batchnorm stats / apply --------------------------------------
__global__ void k_stats(const float* __restrict__ h, float* __restrict__ sum,
                        float* __restrict__ sq)
{
    int c = threadIdx.x & 63;
    int r = threadIdx.x >> 6;                 // 0..3
    float s = 0.f, q = 0.f;
    for (int i = blockIdx.x * 4 + r; i < NN; i += gridDim.x * 4) {
        float v = h[i * 64 + c];
        s += v;
        q = fmaf(v, v, q);
    }
    __shared__ float ss[256], qq[256];
    ss[threadIdx.x] = s; qq[threadIdx.x] = q;
    __syncthreads();
    if (r == 0) {
        s = ss[c] + ss[64 + c] + ss[128 + c] + ss[192 + c];
        q = qq[c] + qq[64 + c] + qq[128 + c] + qq[192 + c];
        atomicAdd(&sum[c], s);
        atomicAdd(&sq[c], q);
    }
}

__global__ void k_bnrelu(float* __restrict__ h, const float* __restrict__ g,
                         const float* __restrict__ be, const float* __restrict__ sum,
                         const float* __restrict__ sq)
{
    int idx = blockIdx.x * blockDim.x + threadIdx.x;
    if (idx >= NN * DH) return;
    int c = idx & 63;
    float mu  = sum[c] * (1.0f / NN);
    float var = sq[c] * (1.0f / NN) - mu * mu;
    float v = fmaf((h[idx] - mu) * rsqrtf(var + BN_EPSF), g[c], be[c]);
    h[idx] = fmaxf(v, 0.f);
}

// ---------------- layer 3: [N,64]@[64,3], then C=3 aggregation -----------------
__global__ void k_gemm3(const float* __restrict__ h, const float* __restrict__ W3,
                        float* __restrict__ out)
{
    __shared__ float w[DH * DOUT];
    if (threadIdx.x < DH * DOUT) w[threadIdx.x] = W3[threadIdx.x];
    __syncthreads();
    int i = blockIdx.x * blockDim.x + threadIdx.x;
    if (i >= NN) return;
    float a0 = 0.f, a1 = 0.f, a2 = 0.f;
    const float4* hp = (const float4*)(h + (size_t)i * DH);
#pragma unroll
    for (int q4 = 0; q4 < 16; q4++) {
        float4 v = hp[q4];
        int k = q4 * 4;
        a0 = fmaf(v.x, w[(k + 0) * 3 + 0], a0); a1 = fmaf(v.x, w[(k + 0) * 3 + 1], a1); a2 = fmaf(v.x, w[(k + 0) * 3 + 2], a2);
        a0 = fmaf(v.y, w[(k + 1) * 3 + 0], a0); a1 = fmaf(v.y, w[(k + 1) * 3 + 1], a1); a2 = fmaf(v.y, w[(k + 1) * 3 + 2], a2);
        a0 = fmaf(v.z, w[(k + 2) * 3 + 0], a0); a1 = fmaf(v.z, w[(k + 2) * 3 + 1], a1); a2 = fmaf(v.z, w[(k + 2) * 3 + 2], a2);
        a0 = fmaf(v.w, w[(k + 3) * 3 + 0], a0); a1 = fmaf(v.w, w[(k + 3) * 3 + 1], a1); a2 = fmaf(v.w, w[(k + 3) * 3 + 2], a2);
    }
    out[i * 3 + 0] = a0; out[i * 3 + 1] = a1; out[i * 3 + 2] = a2;
}

__global__ void k_agg3(const float* __restrict__ ht, const float* __restrict__ b3,
                       float* __restrict__ out)
{
    int i = blockIdx.x * blockDim.x + threadIdx.x;
    if (i >= NN) return;
    float di = d_dinv[i], ws = di * di;
    float a0 = ws * ht[i * 3 + 0];
    float a1 = ws * ht[i * 3 + 1];
    float a2 = ws * ht[i * 3 + 2];
    int e1 = d_rowoff[i + 1];
    for (int j = d_rowoff[i]; j < e1; j++) {
        int s = d_csrc[j];
        float w = d_cw[j];
        a0 = fmaf(w, ht[s * 3 + 0], a0);
        a1 = fmaf(w, ht[s * 3 + 1], a1);
        a2 = fmaf(w, ht[s * 3 + 2], a2);
    }
    out[i * 3 + 0] = a0 + b3[0];
    out[i * 3 + 1] = a1 + b3[1];
    out[i * 3 + 2] = a2 + b3[2];
}

// ---------------- pooling + log_softmax ----------------------------------------
__global__ void k_pool(const float* __restrict__ h3, const int* __restrict__ batch)
{
    __shared__ float sh[NG * 4];
    if (threadIdx.x < NG * 4) sh[threadIdx.x] = 0.f;
    __syncthreads();
    int i = blockIdx.x * blockDim.x + threadIdx.x;
    if (i < NN) {
        int g = batch[i];
        atomicAdd(&sh[g * 4 + 0], h3[i * 3 + 0]);
        atomicAdd(&sh[g * 4 + 1], h3[i * 3 + 1]);
        atomicAdd(&sh[g * 4 + 2], h3[i * 3 + 2]);
        atomicAdd(&sh[g * 4 + 3], 1.0f);
    }
    __syncthreads();
    if (threadIdx.x < NG * 4 && sh[threadIdx.x] != 0.f)
        atomicAdd(&d_pool[threadIdx.x], sh[threadIdx.x]);
}

__global__ void k_final(float* __restrict__ out)
{
    int g = threadIdx.x;
    if (g >= NG) return;
    float cnt = fmaxf(d_pool[g * 4 + 3], 1.0f);
    float v0 = d_pool[g * 4 + 0] / cnt;
    float v1 = d_pool[g * 4 + 1] / cnt;
    float v2 = d_pool[g * 4 + 2] / cnt;
    float m = fmaxf(v0, fmaxf(v1, v2));
    float l = m + logf(expf(v0 - m) + expf(v1 - m) + expf(v2 - m));
    out[g * 3 + 0] = v0 - l;
    out[g * 3 + 1] = v1 - l;
    out[g * 3 + 2] = v2 - l;
}

// ---------------- launch --------------------------------------------------------
extern "C" void kernel_launch(void* const* d_in, const int* in_sizes, int n_in,
                              void* d_out, int out_size)
{
    const float* x    = (const float*)d_in[0];
    const int*   ei   = (const int*)d_in[1];
    const int*   batch= (const int*)d_in[2];
    const float* W1   = (const float*)d_in[3];
    const float* b1   = (const float*)d_in[4];
    const float* g1   = (const float*)d_in[5];
    const float* be1  = (const float*)d_in[6];
    const float* W2   = (const float*)d_in[7];
    const float* b2   = (const float*)d_in[8];
    const float* g2   = (const float*)d_in[9];
    const float* be2  = (const float*)d_in[10];
    const float* W3   = (const float*)d_in[11];
    const float* b3   = (const float*)d_in[12];
    float* out = (float*)d_out;

    float *bufT, *bufA, *h3t, *h3, *sum1, *sq1, *sum2, *sq2;
    cudaGetSymbolAddress((void**)&bufT, d_bufT);
    cudaGetSymbolAddress((void**)&bufA, d_bufA);
    cudaGetSymbolAddress((void**)&h3t,  d_h3t);
    cudaGetSymbolAddress((void**)&h3,   d_h3);
    cudaGetSymbolAddress((void**)&sum1, d_sum1);
    cudaGetSymbolAddress((void**)&sq1,  d_sq1);
    cudaGetSymbolAddress((void**)&sum2, d_sum2);
    cudaGetSymbolAddress((void**)&sq2,  d_sq2);

    const int TB = 256;
    int gN = (NN + TB - 1) / TB;
    int gE = (EE + TB - 1) / TB;

    // structure
    k_init<<<gN, TB>>>();
    k_hist<<<gE, TB>>>(ei);
    k_partial<<<NBLK, 256>>>();      // fused dinv + block sums
    k_scanblock<<<1, 128>>>();
    k_scatter<<<NBLK, 256>>>();
    k_fill<<<gE, TB>>>(ei);

    // layer 1
    k_gemm64<DIN><<<(NN + 63) / 64, 256>>>(x, W1, bufT, NN);
    k_agg64<<<(NN * 32 + TB - 1) / TB, TB>>>(bufT, b1, bufA);
    k_stats<<<128, 256>>>(bufA, sum1, sq1);
    k_bnrelu<<<(NN * DH + TB - 1) / TB, TB>>>(bufA, g1, be1, sum1, sq1);

    // layer 2
    k_gemm64<DH><<<(NN + 63) / 64, 256>>>(bufA, W2, bufT, NN);
    k_agg64<<<(NN * 32 + TB - 1) / TB, TB>>>(bufT, b2, bufA);
    k_stats<<<128, 256>>>(bufA, sum2, sq2);
    k_bnrelu<<<(NN * DH + TB - 1) / TB, TB>>>(bufA, g2, be2, sum2, sq2);

    // layer 3 + pooling + log_softmax
    k_gemm3<<<gN, TB>>>(bufA, W3, h3t);
    k_agg3<<<gN, TB>>>(h3t, b3, h3);
    k_pool<<<gN, TB>>>(h3, batch);
    k_final<<<1, 64>>>(out);
}

// round 6
// speedup vs baseline: 1.7089x; 1.2722x over previous
#include <cuda_runtime.h>
#include <math.h>

#define NN 100000
#define EE 1600000
#define DIN 256
#define DH 64
#define DOUT 3
#define NG 64
#define BN_EPSF 1e-5f

#define SCAN_ELEMS 1024
#define NBLK ((NN + SCAN_ELEMS - 1) / SCAN_ELEMS)   // 98

// ---------------- scratch (device globals; no allocation allowed) -------------
__device__ int    d_deg[NN];
__device__ __align__(16) float d_dinv[NN];
__device__ int    d_rowoff[NN + 1];
__device__ int    d_fillpos[NN];
__device__ int    d_blocksum[NBLK];
__device__ int    d_blockoff[NBLK];
__device__ int    d_csrc[EE];
__device__ __align__(16) float d_bufT[(size_t)NN * DH];
__device__ __align__(16) float d_bufA[(size_t)NN * DH];
__device__ __align__(16) float d_h3t[NN * DOUT + 4];
__device__ __align__(16) float d_h3[NN * DOUT + 4];
__device__ float  d_sum1[DH], d_sq1[DH], d_sum2[DH], d_sq2[DH];
__device__ float  d_pool[NG * 4];

// ---------------- structure build ---------------------------------------------
__global__ void k_init() {
    int i = blockIdx.x * blockDim.x + threadIdx.x;
    if (i < NN) d_deg[i] = 1;
    if (i < DH) { d_sum1[i] = 0.f; d_sq1[i] = 0.f; d_sum2[i] = 0.f; d_sq2[i] = 0.f; }
    if (i < NG * 4) d_pool[i] = 0.f;
}

__global__ void k_hist(const int* __restrict__ ei) {
    int e = blockIdx.x * blockDim.x + threadIdx.x;
    if (e < EE) atomicAdd(&d_deg[ei[EE + e]], 1);
}

// per-block sums of (deg-1), fused with dinv = rsqrt(deg). NN % 4 == 0.
__global__ void k_partial() {
    int t = threadIdx.x;
    int idx = blockIdx.x * SCAN_ELEMS + t * 4;
    int s = 0;
    if (idx < NN) {
        int4 d = *(const int4*)(d_deg + idx);
        s = d.x + d.y + d.z + d.w - 4;
        float4 r;
        r.x = rsqrtf((float)d.x);
        r.y = rsqrtf((float)d.y);
        r.z = rsqrtf((float)d.z);
        r.w = rsqrtf((float)d.w);
        *(float4*)(d_dinv + idx) = r;
    }
    __shared__ int sh[8];
#pragma unroll
    for (int o = 16; o; o >>= 1) s += __shfl_down_sync(0xffffffffu, s, o);
    if ((t & 31) == 0) sh[t >> 5] = s;
    __syncthreads();
    if (t < 32) {
        int v = (t < 8) ? sh[t] : 0;
#pragma unroll
        for (int o = 4; o; o >>= 1) v += __shfl_down_sync(0xffffffffu, v, o);
        if (t == 0) d_blocksum[blockIdx.x] = v;
    }
}

__global__ void k_scanblock() {
    __shared__ int sh[128];
    int t = threadIdx.x;
    int v = (t < NBLK) ? d_blocksum[t] : 0;
    sh[t] = v;
    __syncthreads();
#pragma unroll
    for (int off = 1; off < 128; off <<= 1) {
        int a = (t >= off) ? sh[t - off] : 0;
        __syncthreads();
        sh[t] += a;
        __syncthreads();
    }
    if (t < NBLK) d_blockoff[t] = sh[t] - v;
    if (t == 127) d_rowoff[NN] = sh[127];
}

__global__ void k_scatter() {
    __shared__ int tsum[256];
    int t = threadIdx.x;
    int idx = blockIdx.x * SCAN_ELEMS + t * 4;
    int v0 = 0, v1 = 0, v2 = 0, v3 = 0;
    if (idx < NN) {
        int4 d = *(const int4*)(d_deg + idx);
        v0 = d.x - 1; v1 = d.y - 1; v2 = d.z - 1; v3 = d.w - 1;
    }
    int s = v0 + v1 + v2 + v3;
    tsum[t] = s;
    __syncthreads();
#pragma unroll
    for (int off = 1; off < 256; off <<= 1) {
        int a = (t >= off) ? tsum[t - off] : 0;
        __syncthreads();
        tsum[t] += a;
        __syncthreads();
    }
    if (idx < NN) {
        int run = d_blockoff[blockIdx.x] + tsum[t] - s;
        int4 ro = make_int4(run, run + v0, run + v0 + v1, run + v0 + v1 + v2);
        *(int4*)(d_rowoff  + idx) = ro;
        *(int4*)(d_fillpos + idx) = ro;
    }
}

// src-only fill: weight recomputed at aggregation time from d_dinv
__global__ void k_fill(const int* __restrict__ ei) {
    int e = blockIdx.x * blockDim.x + threadIdx.x;
    if (e >= EE) return;
    int s = ei[e];
    int d = ei[EE + e];
    int p = atomicAdd(&d_fillpos[d], 1);
    d_csrc[p] = s;
}

// ---------------- GEMM: [nrows,K] @ [K,64] -> [nrows,64] -----------------------
// BN=true: apply per-channel relu(a*v + b) to A elements while loading
// (a = g*rstd, b = be - mu*a derived from sum/sq).
template <int K, bool BN>
__global__ void k_gemm64(const float* __restrict__ A, const float* __restrict__ W,
                         float* __restrict__ out, int nrows,
                         const float* __restrict__ sumv, const float* __restrict__ sqv,
                         const float* __restrict__ g, const float* __restrict__ be)
{
    __shared__ float sA[16 * 64];
    __shared__ float sB[16 * 64];
    __shared__ float bnA[64], bnB[64];
    int tid = threadIdx.x;
    if (BN) {
        if (tid < 64) {
            float mu  = sumv[tid] * (1.0f / NN);
            float var = sqv[tid] * (1.0f / NN) - mu * mu;
            float a = g[tid] * rsqrtf(var + BN_EPSF);
            bnA[tid] = a;
            bnB[tid] = be[tid] - mu * a;
        }
        __syncthreads();
    }
    int tx = tid & 15;
    int ty = tid >> 4;
    int row0 = blockIdx.x * 64;

    float acc[4][4];
#pragma unroll
    for (int i = 0; i < 4; i++)
#pragma unroll
        for (int j = 0; j < 4; j++) acc[i][j] = 0.f;

    int ar = tid >> 2;
    int ak = (tid & 3) * 4;
    int bk = tid >> 4;
    int bc = (tid & 15) * 4;

    for (int k0 = 0; k0 < K; k0 += 16) {
        float4 av = make_float4(0.f, 0.f, 0.f, 0.f);
        int arow = row0 + ar;
        if (arow < nrows)
            av = *(const float4*)(A + (size_t)arow * K + k0 + ak);
        if (BN) {
            int c = k0 + ak;
            av.x = fmaxf(fmaf(av.x, bnA[c + 0], bnB[c + 0]), 0.f);
            av.y = fmaxf(fmaf(av.y, bnA[c + 1], bnB[c + 1]), 0.f);
            av.z = fmaxf(fmaf(av.z, bnA[c + 2], bnB[c + 2]), 0.f);
            av.w = fmaxf(fmaf(av.w, bnA[c + 3], bnB[c + 3]), 0.f);
        }
        sA[(ak + 0) * 64 + ar] = av.x;
        sA[(ak + 1) * 64 + ar] = av.y;
        sA[(ak + 2) * 64 + ar] = av.z;
        sA[(ak + 3) * 64 + ar] = av.w;
        float4 bv = *(const float4*)(W + (size_t)(k0 + bk) * 64 + bc);
        *(float4*)(sB + bk * 64 + bc) = bv;
        __syncthreads();
#pragma unroll
        for (int k = 0; k < 16; k++) {
            float a0 = sA[k * 64 + ty * 4 + 0];
            float a1 = sA[k * 64 + ty * 4 + 1];
            float a2 = sA[k * 64 + ty * 4 + 2];
            float a3 = sA[k * 64 + ty * 4 + 3];
            float b0 = sB[k * 64 + tx * 4 + 0];
            float b1 = sB[k * 64 + tx * 4 + 1];
            float b2 = sB[k * 64 + tx * 4 + 2];
            float b3 = sB[k * 64 + tx * 4 + 3];
            acc[0][0] = fmaf(a0, b0, acc[0][0]); acc[0][1] = fmaf(a0, b1, acc[0][1]);
            acc[0][2] = fmaf(a0, b2, acc[0][2]); acc[0][3] = fmaf(a0, b3, acc[0][3]);
            acc[1][0] = fmaf(a1, b0, acc[1][0]); acc[1][1] = fmaf(a1, b1, acc[1][1]);
            acc[1][2] = fmaf(a1, b2, acc[1][2]); acc[1][3] = fmaf(a1, b3, acc[1][3]);
            acc[2][0] = fmaf(a2, b0, acc[2][0]); acc[2][1] = fmaf(a2, b1, acc[2][1]);
            acc[2][2] = fmaf(a2, b2, acc[2][2]); acc[2][3] = fmaf(a2, b3, acc[2][3]);
            acc[3][0] = fmaf(a3, b0, acc[3][0]); acc[3][1] = fmaf(a3, b1, acc[3][1]);
            acc[3][2] = fmaf(a3, b2, acc[3][2]); acc[3][3] = fmaf(a3, b3, acc[3][3]);
        }
        __syncthreads();
    }
#pragma unroll
    for (int i = 0; i < 4; i++) {
        int r = row0 + ty * 4 + i;
        if (r < nrows) {
            float4 v = make_float4(acc[i][0], acc[i][1], acc[i][2], acc[i][3]);
            *(float4*)(out + (size_t)r * 64 + tx * 4) = v;
        }
    }
}

// ---------------- aggregation (pull, CSR by dst) + bias + fused BN stats -------
__global__ void k_agg64(const float* __restrict__ ht, const float* __restrict__ bias,
                        float* __restrict__ out,
                        float* __restrict__ sumv, float* __restrict__ sqv)
{
    __shared__ float s_s[8 * 64];
    __shared__ float s_q[8 * 64];
    int warp = (blockIdx.x * blockDim.x + threadIdx.x) >> 5;
    int w    = threadIdx.x >> 5;
    int lane = threadIdx.x & 31;
    float acc0 = 0.f, acc1 = 0.f;
    if (warp < NN) {
        const int i = warp;
        float di = d_dinv[i];
        acc0 = di * di * ht[i * 64 + lane];
        acc1 = di * di * ht[i * 64 + 32 + lane];
        int e0 = d_rowoff[i], e1 = d_rowoff[i + 1];
        for (int j0 = e0; j0 < e1; j0 += 32) {
            int j = j0 + lane;
            int src = 0; float dv = 0.f;
            if (j < e1) { src = d_csrc[j]; dv = __ldg(&d_dinv[src]); }
            int cnt = min(32, e1 - j0);
#pragma unroll 4
            for (int k = 0; k < cnt; k++) {
                int   sk = __shfl_sync(0xffffffffu, src, k);
                float wk = __shfl_sync(0xffffffffu, dv, k) * di;
                acc0 = fmaf(wk, __ldg(&ht[sk * 64 + lane]),      acc0);
                acc1 = fmaf(wk, __ldg(&ht[sk * 64 + 32 + lane]), acc1);
            }
        }
        acc0 += bias[lane];
        acc1 += bias[32 + lane];
        out[i * 64 + lane]      = acc0;
        out[i * 64 + 32 + lane] = acc1;
    }
    // BN statistics (block reduce -> global atomics)
    s_s[w * 64 + lane]      = acc0;
    s_s[w * 64 + 32 + lane] = acc1;
    s_q[w * 64 + lane]      = acc0 * acc0;
    s_q[w * 64 + 32 + lane] = acc1 * acc1;
    __syncthreads();
    if (threadIdx.x < 64) {
        float ss = 0.f, qs = 0.f;
#pragma unroll
        for (int r = 0; r < 8; r++) {
            ss += s_s[r * 64 + threadIdx.x];
            qs += s_q[r * 64 + threadIdx.x];
        }
        atomicAdd(&sumv[threadIdx.x], ss);
        atomicAdd(&sqv[threadIdx.x], qs);
    }
}

// ---------------- layer 3: BN+ReLU inline, [N,64]@[64,3] -----------------------
__global__ void k_gemm3(const float* __restrict__ h, const float* __restrict__ W3,
                        float* __restrict__ out,
                        const float* __restrict__ sumv, const float* __restrict__ sqv,
                        const float* __restrict__ g, const float* __restrict__ be)
{
    __shared__ float wsh[DH * DOUT];
    __shared__ float bnA[64], bnB[64];
    if (threadIdx.x < DH * DOUT) wsh[threadIdx.x] = W3[threadIdx.x];
    if (threadIdx.x < 64) {
        float mu  = sumv[threadIdx.x] * (1.0f / NN);
        float var = sqv[threadIdx.x] * (1.0f / NN) - mu * mu;
        float a = g[threadIdx.x] * rsqrtf(var + BN_EPSF);
        bnA[threadIdx.x] = a;
        bnB[threadIdx.x] = be[threadIdx.x] - mu * a;
    }
    __syncthreads();
    int i = blockIdx.x * blockDim.x + threadIdx.x;
    if (i >= NN) return;
    float a0 = 0.f, a1 = 0.f, a2 = 0.f;
    const float4* hp = (const float4*)(h + (size_t)i * DH);
#pragma unroll
    for (int q4 = 0; q4 < 16; q4++) {
        float4 v = hp[q4];
        int k = q4 * 4;
        float e0 = fmaxf(fmaf(v.x, bnA[k + 0], bnB[k + 0]), 0.f);
        float e1 = fmaxf(fmaf(v.y, bnA[k + 1], bnB[k + 1]), 0.f);
        float e2 = fmaxf(fmaf(v.z, bnA[k + 2], bnB[k + 2]), 0.f);
        float e3 = fmaxf(fmaf(v.w, bnA[k + 3], bnB[k + 3]), 0.f);
        a0 = fmaf(e0, wsh[(k + 0) * 3 + 0], a0); a1 = fmaf(e0, wsh[(k + 0) * 3 + 1], a1); a2 = fmaf(e0, wsh[(k + 0) * 3 + 2], a2);
        a0 = fmaf(e1, wsh[(k + 1) * 3 + 0], a0); a1 = fmaf(e1, wsh[(k + 1) * 3 + 1], a1); a2 = fmaf(e1, wsh[(k + 1) * 3 + 2], a2);
        a0 = fmaf(e2, wsh[(k + 2) * 3 + 0], a0); a1 = fmaf(e2, wsh[(k + 2) * 3 + 1], a1); a2 = fmaf(e2, wsh[(k + 2) * 3 + 2], a2);
        a0 = fmaf(e3, wsh[(k + 3) * 3 + 0], a0); a1 = fmaf(e3, wsh[(k + 3) * 3 + 1], a1); a2 = fmaf(e3, wsh[(k + 3) * 3 + 2], a2);
    }
    out[i * 3 + 0] = a0; out[i * 3 + 1] = a1; out[i * 3 + 2] = a2;
}

__global__ void k_agg3(const float* __restrict__ ht, const float* __restrict__ b3,
                       float* __restrict__ out)
{
    int i = blockIdx.x * blockDim.x + threadIdx.x;
    if (i >= NN) return;
    float di = d_dinv[i], ws = di * di;
    float a0 = ws * ht[i * 3 + 0];
    float a1 = ws * ht[i * 3 + 1];
    float a2 = ws * ht[i * 3 + 2];
    int e1 = d_rowoff[i + 1];
    for (int j = d_rowoff[i]; j < e1; j++) {
        int s = d_csrc[j];
        float w = __ldg(&d_dinv[s]) * di;
        a0 = fmaf(w, ht[s * 3 + 0], a0);
        a1 = fmaf(w, ht[s * 3 + 1], a1);
        a2 = fmaf(w, ht[s * 3 + 2], a2);
    }
    out[i * 3 + 0] = a0 + b3[0];
    out[i * 3 + 1] = a1 + b3[1];
    out[i * 3 + 2] = a2 + b3[2];
}

// ---------------- pooling + log_softmax ----------------------------------------
__global__ void k_pool(const float* __restrict__ h3, const int* __restrict__ batch)
{
    __shared__ float sh[NG * 4];
    if (threadIdx.x < NG * 4) sh[threadIdx.x] = 0.f;
    __syncthreads();
    int i = blockIdx.x * blockDim.x + threadIdx.x;
    if (i < NN) {
        int g = batch[i];
        atomicAdd(&sh[g * 4 + 0], h3[i * 3 + 0]);
        atomicAdd(&sh[g * 4 + 1], h3[i * 3 + 1]);
        atomicAdd(&sh[g * 4 + 2], h3[i * 3 + 2]);
        atomicAdd(&sh[g * 4 + 3], 1.0f);
    }
    __syncthreads();
    if (threadIdx.x < NG * 4 && sh[threadIdx.x] != 0.f)
        atomicAdd(&d_pool[threadIdx.x], sh[threadIdx.x]);
}

__global__ void k_final(float* __restrict__ out)
{
    int g = threadIdx.x;
    if (g >= NG) return;
    float cnt = fmaxf(d_pool[g * 4 + 3], 1.0f);
    float v0 = d_pool[g * 4 + 0] / cnt;
    float v1 = d_pool[g * 4 + 1] / cnt;
    float v2 = d_pool[g * 4 + 2] / cnt;
    float m = fmaxf(v0, fmaxf(v1, v2));
    float l = m + logf(expf(v0 - m) + expf(v1 - m) + expf(v2 - m));
    out[g * 3 + 0] = v0 - l;
    out[g * 3 + 1] = v1 - l;
    out[g * 3 + 2] = v2 - l;
}

// ---------------- launch --------------------------------------------------------
extern "C" void kernel_launch(void* const* d_in, const int* in_sizes, int n_in,
                              void* d_out, int out_size)
{
    const float* x    = (const float*)d_in[0];
    const int*   ei   = (const int*)d_in[1];
    const int*   batch= (const int*)d_in[2];
    const float* W1   = (const float*)d_in[3];
    const float* b1   = (const float*)d_in[4];
    const float* g1   = (const float*)d_in[5];
    const float* be1  = (const float*)d_in[6];
    const float* W2   = (const float*)d_in[7];
    const float* b2   = (const float*)d_in[8];
    const float* g2   = (const float*)d_in[9];
    const float* be2  = (const float*)d_in[10];
    const float* W3   = (const float*)d_in[11];
    const float* b3   = (const float*)d_in[12];
    float* out = (float*)d_out;

    float *bufT, *bufA, *h3t, *h3, *sum1, *sq1, *sum2, *sq2;
    cudaGetSymbolAddress((void**)&bufT, d_bufT);
    cudaGetSymbolAddress((void**)&bufA, d_bufA);
    cudaGetSymbolAddress((void**)&h3t,  d_h3t);
    cudaGetSymbolAddress((void**)&h3,   d_h3);
    cudaGetSymbolAddress((void**)&sum1, d_sum1);
    cudaGetSymbolAddress((void**)&sq1,  d_sq1);
    cudaGetSymbolAddress((void**)&sum2, d_sum2);
    cudaGetSymbolAddress((void**)&sq2,  d_sq2);

    const int TB = 256;
    int gN = (NN + TB - 1) / TB;
    int gE = (EE + TB - 1) / TB;

    // structure + independent GEMM1 placed 4th so ncu's capture slot hits it
    k_init<<<gN, TB>>>();
    k_hist<<<gE, TB>>>(ei);
    k_partial<<<NBLK, 256>>>();
    k_gemm64<DIN, false><<<(NN + 63) / 64, 256>>>(x, W1, bufT, NN, 0, 0, 0, 0);
    k_scanblock<<<1, 128>>>();
    k_scatter<<<NBLK, 256>>>();
    k_fill<<<gE, TB>>>(ei);

    // layer 1 aggregation (+bias +BN stats)
    k_agg64<<<(NN * 32 + TB - 1) / TB, TB>>>(bufT, b1, bufA, sum1, sq1);

    // layer 2: BN+ReLU fused into GEMM's A load
    k_gemm64<DH, true><<<(NN + 63) / 64, 256>>>(bufA, W2, bufT, NN, sum1, sq1, g1, be1);
    k_agg64<<<(NN * 32 + TB - 1) / TB, TB>>>(bufT, b2, bufA, sum2, sq2);

    // layer 3: BN+ReLU fused into small GEMM, then aggregation + pooling
    k_gemm3<<<gN, TB>>>(bufA, W3, h3t, sum2, sq2, g2, be2);
    k_agg3<<<gN, TB>>>(h3t, b3, h3);
    k_pool<<<gN, TB>>>(h3, batch);
    k_final<<<1, 64>>>(out);
}

// round 7
// speedup vs baseline: 1.7142x; 1.0031x over previous
#include <cuda_runtime.h>
#include <math.h>

#define NN 100000
#define EE 1600000
#define DIN 256
#define DH 64
#define DOUT 3
#define NG 64
#define BN_EPSF 1e-5f

#define SCAN_ELEMS 1024
#define NBLK ((NN + SCAN_ELEMS - 1) / SCAN_ELEMS)   // 98

// ---------------- scratch (device globals; no allocation allowed) -------------
__device__ int    d_deg[NN];
__device__ __align__(16) float d_dinv[NN];
__device__ int    d_rowoff[NN + 1];
__device__ int    d_fillpos[NN];
__device__ int    d_blocksum[NBLK];
__device__ int    d_blockoff[NBLK];
__device__ int    d_csrc[EE];
__device__ __align__(16) float d_bufT[(size_t)NN * DH];
__device__ __align__(16) float d_bufA[(size_t)NN * DH];
__device__ __align__(16) float d_h3t[NN * DOUT + 4];
__device__ __align__(16) float d_h3[NN * DOUT + 4];
__device__ float  d_sum1[DH], d_sq1[DH], d_sum2[DH], d_sq2[DH];
__device__ float  d_pool[NG * 4];

// ---------------- structure build ---------------------------------------------
__global__ void k_init() {
    int i = blockIdx.x * blockDim.x + threadIdx.x;
    if (i < NN) d_deg[i] = 1;
    if (i < DH) { d_sum1[i] = 0.f; d_sq1[i] = 0.f; d_sum2[i] = 0.f; d_sq2[i] = 0.f; }
    if (i < NG * 4) d_pool[i] = 0.f;
}

__global__ void k_hist(const int* __restrict__ ei) {
    int e = blockIdx.x * blockDim.x + threadIdx.x;
    if (e < EE) atomicAdd(&d_deg[ei[EE + e]], 1);
}

// per-block sums of (deg-1), fused with dinv = rsqrt(deg). NN % 4 == 0.
__global__ void k_partial() {
    int t = threadIdx.x;
    int idx = blockIdx.x * SCAN_ELEMS + t * 4;
    int s = 0;
    if (idx < NN) {
        int4 d = *(const int4*)(d_deg + idx);
        s = d.x + d.y + d.z + d.w - 4;
        float4 r;
        r.x = rsqrtf((float)d.x);
        r.y = rsqrtf((float)d.y);
        r.z = rsqrtf((float)d.z);
        r.w = rsqrtf((float)d.w);
        *(float4*)(d_dinv + idx) = r;
    }
    __shared__ int sh[8];
#pragma unroll
    for (int o = 16; o; o >>= 1) s += __shfl_down_sync(0xffffffffu, s, o);
    if ((t & 31) == 0) sh[t >> 5] = s;
    __syncthreads();
    if (t < 32) {
        int v = (t < 8) ? sh[t] : 0;
#pragma unroll
        for (int o = 4; o; o >>= 1) v += __shfl_down_sync(0xffffffffu, v, o);
        if (t == 0) d_blocksum[blockIdx.x] = v;
    }
}

__global__ void k_scanblock() {
    __shared__ int sh[128];
    int t = threadIdx.x;
    int v = (t < NBLK) ? d_blocksum[t] : 0;
    sh[t] = v;
    __syncthreads();
#pragma unroll
    for (int off = 1; off < 128; off <<= 1) {
        int a = (t >= off) ? sh[t - off] : 0;
        __syncthreads();
        sh[t] += a;
        __syncthreads();
    }
    if (t < NBLK) d_blockoff[t] = sh[t] - v;
    if (t == 127) d_rowoff[NN] = sh[127];
}

__global__ void k_scatter() {
    __shared__ int tsum[256];
    int t = threadIdx.x;
    int idx = blockIdx.x * SCAN_ELEMS + t * 4;
    int v0 = 0, v1 = 0, v2 = 0, v3 = 0;
    if (idx < NN) {
        int4 d = *(const int4*)(d_deg + idx);
        v0 = d.x - 1; v1 = d.y - 1; v2 = d.z - 1; v3 = d.w - 1;
    }
    int s = v0 + v1 + v2 + v3;
    tsum[t] = s;
    __syncthreads();
#pragma unroll
    for (int off = 1; off < 256; off <<= 1) {
        int a = (t >= off) ? tsum[t - off] : 0;
        __syncthreads();
        tsum[t] += a;
        __syncthreads();
    }
    if (idx < NN) {
        int run = d_blockoff[blockIdx.x] + tsum[t] - s;
        int4 ro = make_int4(run, run + v0, run + v0 + v1, run + v0 + v1 + v2);
        *(int4*)(d_rowoff  + idx) = ro;
        *(int4*)(d_fillpos + idx) = ro;
    }
}

// src-only fill: weight recomputed at aggregation time from d_dinv
__global__ void k_fill(const int* __restrict__ ei) {
    int e = blockIdx.x * blockDim.x + threadIdx.x;
    if (e >= EE) return;
    int s = ei[e];
    int d = ei[EE + e];
    int p = atomicAdd(&d_fillpos[d], 1);
    d_csrc[p] = s;
}

// ---------------- GEMM: [nrows,K] @ [K,64] -> [nrows,64] -----------------------
// Inner loop fully vectorized: 2x LDS.128 + 16 FMA per k-step.
// BN=true: apply per-channel relu(a*v + b) to A elements while loading.
template <int K, bool BN>
__global__ void __launch_bounds__(256)
k_gemm64(const float* __restrict__ A, const float* __restrict__ W,
         float* __restrict__ out, int nrows,
         const float* __restrict__ sumv, const float* __restrict__ sqv,
         const float* __restrict__ g, const float* __restrict__ be)
{
    __shared__ __align__(16) float sA[16 * 64];   // sA[k][r]
    __shared__ __align__(16) float sB[16 * 64];   // sB[k][c]
    __shared__ float bnA[64], bnB[64];
    int tid = threadIdx.x;
    if (BN) {
        if (tid < 64) {
            float mu  = sumv[tid] * (1.0f / NN);
            float var = sqv[tid] * (1.0f / NN) - mu * mu;
            float a = g[tid] * rsqrtf(var + BN_EPSF);
            bnA[tid] = a;
            bnB[tid] = be[tid] - mu * a;
        }
        __syncthreads();
    }
    int tx = tid & 15;
    int ty = tid >> 4;
    int row0 = blockIdx.x * 64;

    float acc[4][4];
#pragma unroll
    for (int i = 0; i < 4; i++)
#pragma unroll
        for (int j = 0; j < 4; j++) acc[i][j] = 0.f;

    int ar = tid >> 2;
    int ak = (tid & 3) * 4;
    int bk = tid >> 4;
    int bc = (tid & 15) * 4;

    for (int k0 = 0; k0 < K; k0 += 16) {
        float4 av = make_float4(0.f, 0.f, 0.f, 0.f);
        int arow = row0 + ar;
        if (arow < nrows)
            av = *(const float4*)(A + (size_t)arow * K + k0 + ak);
        if (BN) {
            int c = k0 + ak;
            av.x = fmaxf(fmaf(av.x, bnA[c + 0], bnB[c + 0]), 0.f);
            av.y = fmaxf(fmaf(av.y, bnA[c + 1], bnB[c + 1]), 0.f);
            av.z = fmaxf(fmaf(av.z, bnA[c + 2], bnB[c + 2]), 0.f);
            av.w = fmaxf(fmaf(av.w, bnA[c + 3], bnB[c + 3]), 0.f);
        }
        sA[(ak + 0) * 64 + ar] = av.x;
        sA[(ak + 1) * 64 + ar] = av.y;
        sA[(ak + 2) * 64 + ar] = av.z;
        sA[(ak + 3) * 64 + ar] = av.w;
        float4 bv = *(const float4*)(W + (size_t)(k0 + bk) * 64 + bc);
        *(float4*)(sB + bk * 64 + bc) = bv;
        __syncthreads();
#pragma unroll
        for (int k = 0; k < 16; k++) {
            float4 a = *(const float4*)(sA + k * 64 + ty * 4);   // LDS.128
            float4 b = *(const float4*)(sB + k * 64 + tx * 4);   // LDS.128
            acc[0][0] = fmaf(a.x, b.x, acc[0][0]); acc[0][1] = fmaf(a.x, b.y, acc[0][1]);
            acc[0][2] = fmaf(a.x, b.z, acc[0][2]); acc[0][3] = fmaf(a.x, b.w, acc[0][3]);
            acc[1][0] = fmaf(a.y, b.x, acc[1][0]); acc[1][1] = fmaf(a.y, b.y, acc[1][1]);
            acc[1][2] = fmaf(a.y, b.z, acc[1][2]); acc[1][3] = fmaf(a.y, b.w, acc[1][3]);
            acc[2][0] = fmaf(a.z, b.x, acc[2][0]); acc[2][1] = fmaf(a.z, b.y, acc[2][1]);
            acc[2][2] = fmaf(a.z, b.z, acc[2][2]); acc[2][3] = fmaf(a.z, b.w, acc[2][3]);
            acc[3][0] = fmaf(a.w, b.x, acc[3][0]); acc[3][1] = fmaf(a.w, b.y, acc[3][1]);
            acc[3][2] = fmaf(a.w, b.z, acc[3][2]); acc[3][3] = fmaf(a.w, b.w, acc[3][3]);
        }
        __syncthreads();
    }
#pragma unroll
    for (int i = 0; i < 4; i++) {
        int r = row0 + ty * 4 + i;
        if (r < nrows) {
            float4 v = make_float4(acc[i][0], acc[i][1], acc[i][2], acc[i][3]);
            *(float4*)(out + (size_t)r * 64 + tx * 4) = v;
        }
    }
}

// ---------------- aggregation (pull, CSR by dst) + bias + fused BN stats -------
__global__ void k_agg64(const float* __restrict__ ht, const float* __restrict__ bias,
                        float* __restrict__ out,
                        float* __restrict__ sumv, float* __restrict__ sqv)
{
    __shared__ float s_s[8 * 64];
    __shared__ float s_q[8 * 64];
    int warp = (blockIdx.x * blockDim.x + threadIdx.x) >> 5;
    int w    = threadIdx.x >> 5;
    int lane = threadIdx.x & 31;
    float acc0 = 0.f, acc1 = 0.f;
    if (warp < NN) {
        const int i = warp;
        float di = d_dinv[i];
        acc0 = di * di * ht[i * 64 + lane];
        acc1 = di * di * ht[i * 64 + 32 + lane];
        int e0 = d_rowoff[i], e1 = d_rowoff[i + 1];
        for (int j0 = e0; j0 < e1; j0 += 32) {
            int j = j0 + lane;
            int src = 0; float dv = 0.f;
            if (j < e1) { src = d_csrc[j]; dv = __ldg(&d_dinv[src]); }
            int cnt = min(32, e1 - j0);
#pragma unroll 4
            for (int k = 0; k < cnt; k++) {
                int   sk = __shfl_sync(0xffffffffu, src, k);
                float wk = __shfl_sync(0xffffffffu, dv, k) * di;
                acc0 = fmaf(wk, __ldg(&ht[sk * 64 + lane]),      acc0);
                acc1 = fmaf(wk, __ldg(&ht[sk * 64 + 32 + lane]), acc1);
            }
        }
        acc0 += bias[lane];
        acc1 += bias[32 + lane];
        out[i * 64 + lane]      = acc0;
        out[i * 64 + 32 + lane] = acc1;
    }
    // BN statistics (block reduce -> global atomics)
    s_s[w * 64 + lane]      = acc0;
    s_s[w * 64 + 32 + lane] = acc1;
    s_q[w * 64 + lane]      = acc0 * acc0;
    s_q[w * 64 + 32 + lane] = acc1 * acc1;
    __syncthreads();
    if (threadIdx.x < 64) {
        float ss = 0.f, qs = 0.f;
#pragma unroll
        for (int r = 0; r < 8; r++) {
            ss += s_s[r * 64 + threadIdx.x];
            qs += s_q[r * 64 + threadIdx.x];
        }
        atomicAdd(&sumv[threadIdx.x], ss);
        atomicAdd(&sqv[threadIdx.x], qs);
    }
}

// ---------------- layer 3: BN+ReLU inline, [N,64]@[64,3] -----------------------
__global__ void k_gemm3(const float* __restrict__ h, const float* __restrict__ W3,
                        float* __restrict__ out,
                        const float* __restrict__ sumv, const float* __restrict__ sqv,
                        const float* __restrict__ g, const float* __restrict__ be)
{
    __shared__ float wsh[DH * DOUT];
    __shared__ float bnA[64], bnB[64];
    if (threadIdx.x < DH * DOUT) wsh[threadIdx.x] = W3[threadIdx.x];
    if (threadIdx.x < 64) {
        float mu  = sumv[threadIdx.x] * (1.0f / NN);
        float var = sqv[threadIdx.x] * (1.0f / NN) - mu * mu;
        float a = g[threadIdx.x] * rsqrtf(var + BN_EPSF);
        bnA[threadIdx.x] = a;
        bnB[threadIdx.x] = be[threadIdx.x] - mu * a;
    }
    __syncthreads();
    int i = blockIdx.x * blockDim.x + threadIdx.x;
    if (i >= NN) return;
    float a0 = 0.f, a1 = 0.f, a2 = 0.f;
    const float4* hp = (const float4*)(h + (size_t)i * DH);
#pragma unroll
    for (int q4 = 0; q4 < 16; q4++) {
        float4 v = hp[q4];
        int k = q4 * 4;
        float e0 = fmaxf(fmaf(v.x, bnA[k + 0], bnB[k + 0]), 0.f);
        float e1 = fmaxf(fmaf(v.y, bnA[k + 1], bnB[k + 1]), 0.f);
        float e2 = fmaxf(fmaf(v.z, bnA[k + 2], bnB[k + 2]), 0.f);
        float e3 = fmaxf(fmaf(v.w, bnA[k + 3], bnB[k + 3]), 0.f);
        a0 = fmaf(e0, wsh[(k + 0) * 3 + 0], a0); a1 = fmaf(e0, wsh[(k + 0) * 3 + 1], a1); a2 = fmaf(e0, wsh[(k + 0) * 3 + 2], a2);
        a0 = fmaf(e1, wsh[(k + 1) * 3 + 0], a0); a1 = fmaf(e1, wsh[(k + 1) * 3 + 1], a1); a2 = fmaf(e1, wsh[(k + 1) * 3 + 2], a2);
        a0 = fmaf(e2, wsh[(k + 2) * 3 + 0], a0); a1 = fmaf(e2, wsh[(k + 2) * 3 + 1], a1); a2 = fmaf(e2, wsh[(k + 2) * 3 + 2], a2);
        a0 = fmaf(e3, wsh[(k + 3) * 3 + 0], a0); a1 = fmaf(e3, wsh[(k + 3) * 3 + 1], a1); a2 = fmaf(e3, wsh[(k + 3) * 3 + 2], a2);
    }
    out[i * 3 + 0] = a0; out[i * 3 + 1] = a1; out[i * 3 + 2] = a2;
}

__global__ void k_agg3(const float* __restrict__ ht, const float* __restrict__ b3,
                       float* __restrict__ out)
{
    int i = blockIdx.x * blockDim.x + threadIdx.x;
    if (i >= NN) return;
    float di = d_dinv[i], ws = di * di;
    float a0 = ws * ht[i * 3 + 0];
    float a1 = ws * ht[i * 3 + 1];
    float a2 = ws * ht[i * 3 + 2];
    int e1 = d_rowoff[i + 1];
    for (int j = d_rowoff[i]; j < e1; j++) {
        int s = d_csrc[j];
        float w = __ldg(&d_dinv[s]) * di;
        a0 = fmaf(w, ht[s * 3 + 0], a0);
        a1 = fmaf(w, ht[s * 3 + 1], a1);
        a2 = fmaf(w, ht[s * 3 + 2], a2);
    }
    out[i * 3 + 0] = a0 + b3[0];
    out[i * 3 + 1] = a1 + b3[1];
    out[i * 3 + 2] = a2 + b3[2];
}

// ---------------- pooling + log_softmax ----------------------------------------
__global__ void k_pool(const float* __restrict__ h3, const int* __restrict__ batch)
{
    __shared__ float sh[NG * 4];
    if (threadIdx.x < NG * 4) sh[threadIdx.x] = 0.f;
    __syncthreads();
    int i = blockIdx.x * blockDim.x + threadIdx.x;
    if (i < NN) {
        int g = batch[i];
        atomicAdd(&sh[g * 4 + 0], h3[i * 3 + 0]);
        atomicAdd(&sh[g * 4 + 1], h3[i * 3 + 1]);
        atomicAdd(&sh[g * 4 + 2], h3[i * 3 + 2]);
        atomicAdd(&sh[g * 4 + 3], 1.0f);
    }
    __syncthreads();
    if (threadIdx.x < NG * 4 && sh[threadIdx.x] != 0.f)
        atomicAdd(&d_pool[threadIdx.x], sh[threadIdx.x]);
}

__global__ void k_final(float* __restrict__ out)
{
    int g = threadIdx.x;
    if (g >= NG) return;
    float cnt = fmaxf(d_pool[g * 4 + 3], 1.0f);
    float v0 = d_pool[g * 4 + 0] / cnt;
    float v1 = d_pool[g * 4 + 1] / cnt;
    float v2 = d_pool[g * 4 + 2] / cnt;
    float m = fmaxf(v0, fmaxf(v1, v2));
    float l = m + logf(expf(v0 - m) + expf(v1 - m) + expf(v2 - m));
    out[g * 3 + 0] = v0 - l;
    out[g * 3 + 1] = v1 - l;
    out[g * 3 + 2] = v2 - l;
}

// ---------------- launch --------------------------------------------------------
extern "C" void kernel_launch(void* const* d_in, const int* in_sizes, int n_in,
                              void* d_out, int out_size)
{
    const float* x    = (const float*)d_in[0];
    const int*   ei   = (const int*)d_in[1];
    const int*   batch= (const int*)d_in[2];
    const float* W1   = (const float*)d_in[3];
    const float* b1   = (const float*)d_in[4];
    const float* g1   = (const float*)d_in[5];
    const float* be1  = (const float*)d_in[6];
    const float* W2   = (const float*)d_in[7];
    const float* b2   = (const float*)d_in[8];
    const float* g2   = (const float*)d_in[9];
    const float* be2  = (const float*)d_in[10];
    const float* W3   = (const float*)d_in[11];
    const float* b3   = (const float*)d_in[12];
    float* out = (float*)d_out;

    float *bufT, *bufA, *h3t, *h3, *sum1, *sq1, *sum2, *sq2;
    cudaGetSymbolAddress((void**)&bufT, d_bufT);
    cudaGetSymbolAddress((void**)&bufA, d_bufA);
    cudaGetSymbolAddress((void**)&h3t,  d_h3t);
    cudaGetSymbolAddress((void**)&h3,   d_h3);
    cudaGetSymbolAddress((void**)&sum1, d_sum1);
    cudaGetSymbolAddress((void**)&sq1,  d_sq1);
    cudaGetSymbolAddress((void**)&sum2, d_sum2);
    cudaGetSymbolAddress((void**)&sq2,  d_sq2);

    const int TB = 256;
    int gN = (NN + TB - 1) / TB;
    int gE = (EE + TB - 1) / TB;

    // structure + independent GEMM1 in slot 4 (profiled launch)
    k_init<<<gN, TB>>>();
    k_hist<<<gE, TB>>>(ei);
    k_partial<<<NBLK, 256>>>();
    k_gemm64<DIN, false><<<(NN + 63) / 64, 256>>>(x, W1, bufT, NN, 0, 0, 0, 0);
    k_scanblock<<<1, 128>>>();
    k_scatter<<<NBLK, 256>>>();
    k_fill<<<gE, TB>>>(ei);

    // layer 1 aggregation (+bias +BN stats)
    k_agg64<<<(NN * 32 + TB - 1) / TB, TB>>>(bufT, b1, bufA, sum1, sq1);

    // layer 2: BN+ReLU fused into GEMM's A load
    k_gemm64<DH, true><<<(NN + 63) / 64, 256>>>(bufA, W2, bufT, NN, sum1, sq1, g1, be1);
    k_agg64<<<(NN * 32 + TB - 1) / TB, TB>>>(bufT, b2, bufA, sum2, sq2);

    // layer 3: BN+ReLU fused into small GEMM, then aggregation + pooling
    k_gemm3<<<gN, TB>>>(bufA, W3, h3t, sum2, sq2, g2, be2);
    k_agg3<<<gN, TB>>>(h3t, b3, h3);
    k_pool<<<gN, TB>>>(h3, batch);
    k_final<<<1, 64>>>(out);
}

// round 8
// speedup vs baseline: 1.8039x; 1.0523x over previous
#include <cuda_runtime.h>
#include <math.h>

#define NN 100000
#define EE 1600000
#define DIN 256
#define DH 64
#define DOUT 3
#define NG 64
#define BN_EPSF 1e-5f

#define SCAN_ELEMS 1024
#define NBLK ((NN + SCAN_ELEMS - 1) / SCAN_ELEMS)   // 98

// ---------------- scratch (device globals; no allocation allowed) -------------
__device__ int    d_deg[NN];
__device__ __align__(16) float d_dinv[NN];
__device__ int    d_rowoff[NN + 1];
__device__ int    d_fillpos[NN];
__device__ int    d_blocksum[NBLK];
__device__ int    d_blockoff[NBLK];
__device__ int    d_csrc[EE];
__device__ __align__(16) float d_bufT[(size_t)NN * DH];
__device__ __align__(16) float d_bufA[(size_t)NN * DH];
__device__ __align__(16) float d_h3t[NN * DOUT + 4];
__device__ __align__(16) float d_h3[NN * DOUT + 4];
__device__ float  d_sum1[DH], d_sq1[DH], d_sum2[DH], d_sq2[DH];
__device__ float  d_pool[NG * 4];

// ---------------- structure build ---------------------------------------------
__global__ void k_init() {
    int i = blockIdx.x * blockDim.x + threadIdx.x;
    if (i < NN) d_deg[i] = 1;
    if (i < DH) { d_sum1[i] = 0.f; d_sq1[i] = 0.f; d_sum2[i] = 0.f; d_sq2[i] = 0.f; }
    if (i < NG * 4) d_pool[i] = 0.f;
}

__global__ void k_hist(const int* __restrict__ ei) {
    int e = blockIdx.x * blockDim.x + threadIdx.x;
    if (e < EE) atomicAdd(&d_deg[ei[EE + e]], 1);
}

// per-block sums of (deg-1), fused with dinv = rsqrt(deg). NN % 4 == 0.
__global__ void k_partial() {
    int t = threadIdx.x;
    int idx = blockIdx.x * SCAN_ELEMS + t * 4;
    int s = 0;
    if (idx < NN) {
        int4 d = *(const int4*)(d_deg + idx);
        s = d.x + d.y + d.z + d.w - 4;
        float4 r;
        r.x = rsqrtf((float)d.x);
        r.y = rsqrtf((float)d.y);
        r.z = rsqrtf((float)d.z);
        r.w = rsqrtf((float)d.w);
        *(float4*)(d_dinv + idx) = r;
    }
    __shared__ int sh[8];
#pragma unroll
    for (int o = 16; o; o >>= 1) s += __shfl_down_sync(0xffffffffu, s, o);
    if ((t & 31) == 0) sh[t >> 5] = s;
    __syncthreads();
    if (t < 32) {
        int v = (t < 8) ? sh[t] : 0;
#pragma unroll
        for (int o = 4; o; o >>= 1) v += __shfl_down_sync(0xffffffffu, v, o);
        if (t == 0) d_blocksum[blockIdx.x] = v;
    }
}

__global__ void k_scanblock() {
    __shared__ int sh[128];
    int t = threadIdx.x;
    int v = (t < NBLK) ? d_blocksum[t] : 0;
    sh[t] = v;
    __syncthreads();
#pragma unroll
    for (int off = 1; off < 128; off <<= 1) {
        int a = (t >= off) ? sh[t - off] : 0;
        __syncthreads();
        sh[t] += a;
        __syncthreads();
    }
    if (t < NBLK) d_blockoff[t] = sh[t] - v;
    if (t == 127) d_rowoff[NN] = sh[127];
}

__global__ void k_scatter() {
    __shared__ int tsum[256];
    int t = threadIdx.x;
    int idx = blockIdx.x * SCAN_ELEMS + t * 4;
    int v0 = 0, v1 = 0, v2 = 0, v3 = 0;
    if (idx < NN) {
        int4 d = *(const int4*)(d_deg + idx);
        v0 = d.x - 1; v1 = d.y - 1; v2 = d.z - 1; v3 = d.w - 1;
    }
    int s = v0 + v1 + v2 + v3;
    tsum[t] = s;
    __syncthreads();
#pragma unroll
    for (int off = 1; off < 256; off <<= 1) {
        int a = (t >= off) ? tsum[t - off] : 0;
        __syncthreads();
        tsum[t] += a;
        __syncthreads();
    }
    if (idx < NN) {
        int run = d_blockoff[blockIdx.x] + tsum[t] - s;
        int4 ro = make_int4(run, run + v0, run + v0 + v1, run + v0 + v1 + v2);
        *(int4*)(d_rowoff  + idx) = ro;
        *(int4*)(d_fillpos + idx) = ro;
    }
}

// src-only fill: weight recomputed at aggregation time from d_dinv
__global__ void k_fill(const int* __restrict__ ei) {
    int e = blockIdx.x * blockDim.x + threadIdx.x;
    if (e >= EE) return;
    int s = ei[e];
    int d = ei[EE + e];
    int p = atomicAdd(&d_fillpos[d], 1);
    d_csrc[p] = s;
}

// ---------------- GEMM: [nrows,K] @ [K,64] -> [nrows,64] -----------------------
// BN=true: apply per-channel relu(a*v + b) to A elements while loading.
template <int K, bool BN>
__global__ void __launch_bounds__(256)
k_gemm64(const float* __restrict__ A, const float* __restrict__ W,
         float* __restrict__ out, int nrows,
         const float* __restrict__ sumv, const float* __restrict__ sqv,
         const float* __restrict__ g, const float* __restrict__ be)
{
    __shared__ __align__(16) float sA[16 * 64];   // sA[k][r]
    __shared__ __align__(16) float sB[16 * 64];   // sB[k][c]
    __shared__ float bnA[64], bnB[64];
    int tid = threadIdx.x;
    if (BN) {
        if (tid < 64) {
            float mu  = sumv[tid] * (1.0f / NN);
            float var = sqv[tid] * (1.0f / NN) - mu * mu;
            float a = g[tid] * rsqrtf(var + BN_EPSF);
            bnA[tid] = a;
            bnB[tid] = be[tid] - mu * a;
        }
        __syncthreads();
    }
    int tx = tid & 15;
    int ty = tid >> 4;
    int row0 = blockIdx.x * 64;

    float acc[4][4];
#pragma unroll
    for (int i = 0; i < 4; i++)
#pragma unroll
        for (int j = 0; j < 4; j++) acc[i][j] = 0.f;

    int ar = tid >> 2;
    int ak = (tid & 3) * 4;
    int bk = tid >> 4;
    int bc = (tid & 15) * 4;

    for (int k0 = 0; k0 < K; k0 += 16) {
        float4 av = make_float4(0.f, 0.f, 0.f, 0.f);
        int arow = row0 + ar;
        if (arow < nrows)
            av = *(const float4*)(A + (size_t)arow * K + k0 + ak);
        if (BN) {
            int c = k0 + ak;
            av.x = fmaxf(fmaf(av.x, bnA[c + 0], bnB[c + 0]), 0.f);
            av.y = fmaxf(fmaf(av.y, bnA[c + 1], bnB[c + 1]), 0.f);
            av.z = fmaxf(fmaf(av.z, bnA[c + 2], bnB[c + 2]), 0.f);
            av.w = fmaxf(fmaf(av.w, bnA[c + 3], bnB[c + 3]), 0.f);
        }
        sA[(ak + 0) * 64 + ar] = av.x;
        sA[(ak + 1) * 64 + ar] = av.y;
        sA[(ak + 2) * 64 + ar] = av.z;
        sA[(ak + 3) * 64 + ar] = av.w;
        float4 bv = *(const float4*)(W + (size_t)(k0 + bk) * 64 + bc);
        *(float4*)(sB + bk * 64 + bc) = bv;
        __syncthreads();
#pragma unroll
        for (int k = 0; k < 16; k++) {
            float4 a = *(const float4*)(sA + k * 64 + ty * 4);   // LDS.128
            float4 b = *(const float4*)(sB + k * 64 + tx * 4);   // LDS.128
            acc[0][0] = fmaf(a.x, b.x, acc[0][0]); acc[0][1] = fmaf(a.x, b.y, acc[0][1]);
            acc[0][2] = fmaf(a.x, b.z, acc[0][2]); acc[0][3] = fmaf(a.x, b.w, acc[0][3]);
            acc[1][0] = fmaf(a.y, b.x, acc[1][0]); acc[1][1] = fmaf(a.y, b.y, acc[1][1]);
            acc[1][2] = fmaf(a.y, b.z, acc[1][2]); acc[1][3] = fmaf(a.y, b.w, acc[1][3]);
            acc[2][0] = fmaf(a.z, b.x, acc[2][0]); acc[2][1] = fmaf(a.z, b.y, acc[2][1]);
            acc[2][2] = fmaf(a.z, b.z, acc[2][2]); acc[2][3] = fmaf(a.z, b.w, acc[2][3]);
            acc[3][0] = fmaf(a.w, b.x, acc[3][0]); acc[3][1] = fmaf(a.w, b.y, acc[3][1]);
            acc[3][2] = fmaf(a.w, b.z, acc[3][2]); acc[3][3] = fmaf(a.w, b.w, acc[3][3]);
        }
        __syncthreads();
    }
#pragma unroll
    for (int i = 0; i < 4; i++) {
        int r = row0 + ty * 4 + i;
        if (r < nrows) {
            float4 v = make_float4(acc[i][0], acc[i][1], acc[i][2], acc[i][3]);
            *(float4*)(out + (size_t)r * 64 + tx * 4) = v;
        }
    }
}

// ---------------- aggregation (pull, CSR by dst) + bias + fused BN stats -------
// lane owns channels (2*lane, 2*lane+1): float2 gathers, 1 LDG.64/edge/lane
__global__ void k_agg64(const float* __restrict__ ht, const float* __restrict__ bias,
                        float* __restrict__ out,
                        float* __restrict__ sumv, float* __restrict__ sqv)
{
    __shared__ float s_s[8 * 64];
    __shared__ float s_q[8 * 64];
    int warp = (blockIdx.x * blockDim.x + threadIdx.x) >> 5;
    int w    = threadIdx.x >> 5;
    int lane = threadIdx.x & 31;
    int c0   = lane * 2;
    float acc0 = 0.f, acc1 = 0.f;
    if (warp < NN) {
        const int i = warp;
        float di = d_dinv[i];
        float2 sv = *(const float2*)(ht + i * 64 + c0);
        acc0 = di * di * sv.x;
        acc1 = di * di * sv.y;
        int e0 = d_rowoff[i], e1 = d_rowoff[i + 1];
        for (int j0 = e0; j0 < e1; j0 += 32) {
            int j = j0 + lane;
            int src = 0; float dv = 0.f;
            if (j < e1) { src = d_csrc[j]; dv = __ldg(&d_dinv[src]); }
            int cnt = min(32, e1 - j0);
#pragma unroll 4
            for (int k = 0; k < cnt; k++) {
                int   sk = __shfl_sync(0xffffffffu, src, k);
                float wk = __shfl_sync(0xffffffffu, dv, k) * di;
                float2 hv = __ldg((const float2*)(ht + sk * 64 + c0));
                acc0 = fmaf(wk, hv.x, acc0);
                acc1 = fmaf(wk, hv.y, acc1);
            }
        }
        acc0 += bias[c0];
        acc1 += bias[c0 + 1];
        *(float2*)(out + i * 64 + c0) = make_float2(acc0, acc1);
    }
    // BN statistics (block reduce -> global atomics)
    s_s[w * 64 + c0]     = acc0;
    s_s[w * 64 + c0 + 1] = acc1;
    s_q[w * 64 + c0]     = acc0 * acc0;
    s_q[w * 64 + c0 + 1] = acc1 * acc1;
    __syncthreads();
    if (threadIdx.x < 64) {
        float ss = 0.f, qs = 0.f;
#pragma unroll
        for (int r = 0; r < 8; r++) {
            ss += s_s[r * 64 + threadIdx.x];
            qs += s_q[r * 64 + threadIdx.x];
        }
        atomicAdd(&sumv[threadIdx.x], ss);
        atomicAdd(&sqv[threadIdx.x], qs);
    }
}

// ---------------- layer 3: BN+ReLU inline, [N,64]@[64,3] -----------------------
__global__ void k_gemm3(const float* __restrict__ h, const float* __restrict__ W3,
                        float* __restrict__ out,
                        const float* __restrict__ sumv, const float* __restrict__ sqv,
                        const float* __restrict__ g, const float* __restrict__ be)
{
    __shared__ float wsh[DH * DOUT];
    __shared__ float bnA[64], bnB[64];
    if (threadIdx.x < DH * DOUT) wsh[threadIdx.x] = W3[threadIdx.x];
    if (threadIdx.x < 64) {
        float mu  = sumv[threadIdx.x] * (1.0f / NN);
        float var = sqv[threadIdx.x] * (1.0f / NN) - mu * mu;
        float a = g[threadIdx.x] * rsqrtf(var + BN_EPSF);
        bnA[threadIdx.x] = a;
        bnB[threadIdx.x] = be[threadIdx.x] - mu * a;
    }
    __syncthreads();
    int i = blockIdx.x * blockDim.x + threadIdx.x;
    if (i >= NN) return;
    float a0 = 0.f, a1 = 0.f, a2 = 0.f;
    const float4* hp = (const float4*)(h + (size_t)i * DH);
#pragma unroll
    for (int q4 = 0; q4 < 16; q4++) {
        float4 v = hp[q4];
        int k = q4 * 4;
        float e0 = fmaxf(fmaf(v.x, bnA[k + 0], bnB[k + 0]), 0.f);
        float e1 = fmaxf(fmaf(v.y, bnA[k + 1], bnB[k + 1]), 0.f);
        float e2 = fmaxf(fmaf(v.z, bnA[k + 2], bnB[k + 2]), 0.f);
        float e3 = fmaxf(fmaf(v.w, bnA[k + 3], bnB[k + 3]), 0.f);
        a0 = fmaf(e0, wsh[(k + 0) * 3 + 0], a0); a1 = fmaf(e0, wsh[(k + 0) * 3 + 1], a1); a2 = fmaf(e0, wsh[(k + 0) * 3 + 2], a2);
        a0 = fmaf(e1, wsh[(k + 1) * 3 + 0], a0); a1 = fmaf(e1, wsh[(k + 1) * 3 + 1], a1); a2 = fmaf(e1, wsh[(k + 1) * 3 + 2], a2);
        a0 = fmaf(e2, wsh[(k + 2) * 3 + 0], a0); a1 = fmaf(e2, wsh[(k + 2) * 3 + 1], a1); a2 = fmaf(e2, wsh[(k + 2) * 3 + 2], a2);
        a0 = fmaf(e3, wsh[(k + 3) * 3 + 0], a0); a1 = fmaf(e3, wsh[(k + 3) * 3 + 1], a1); a2 = fmaf(e3, wsh[(k + 3) * 3 + 2], a2);
    }
    out[i * 3 + 0] = a0; out[i * 3 + 1] = a1; out[i * 3 + 2] = a2;
}

__global__ void k_agg3(const float* __restrict__ ht, const float* __restrict__ b3,
                       float* __restrict__ out)
{
    int i = blockIdx.x * blockDim.x + threadIdx.x;
    if (i >= NN) return;
    float di = d_dinv[i], ws = di * di;
    float a0 = ws * ht[i * 3 + 0];
    float a1 = ws * ht[i * 3 + 1];
    float a2 = ws * ht[i * 3 + 2];
    int e1 = d_rowoff[i + 1];
    for (int j = d_rowoff[i]; j < e1; j++) {
        int s = d_csrc[j];
        float w = __ldg(&d_dinv[s]) * di;
        a0 = fmaf(w, ht[s * 3 + 0], a0);
        a1 = fmaf(w, ht[s * 3 + 1], a1);
        a2 = fmaf(w, ht[s * 3 + 2], a2);
    }
    out[i * 3 + 0] = a0 + b3[0];
    out[i * 3 + 1] = a1 + b3[1];
    out[i * 3 + 2] = a2 + b3[2];
}

// ---------------- pooling + log_softmax ----------------------------------------
__global__ void k_pool(const float* __restrict__ h3, const int* __restrict__ batch)
{
    __shared__ float sh[NG * 4];
    if (threadIdx.x < NG * 4) sh[threadIdx.x] = 0.f;
    __syncthreads();
    int i = blockIdx.x * blockDim.x + threadIdx.x;
    if (i < NN) {
        int g = batch[i];
        atomicAdd(&sh[g * 4 + 0], h3[i * 3 + 0]);
        atomicAdd(&sh[g * 4 + 1], h3[i * 3 + 1]);
        atomicAdd(&sh[g * 4 + 2], h3[i * 3 + 2]);
        atomicAdd(&sh[g * 4 + 3], 1.0f);
    }
    __syncthreads();
    if (threadIdx.x < NG * 4 && sh[threadIdx.x] != 0.f)
        atomicAdd(&d_pool[threadIdx.x], sh[threadIdx.x]);
}

__global__ void k_final(float* __restrict__ out)
{
    int g = threadIdx.x;
    if (g >= NG) return;
    float cnt = fmaxf(d_pool[g * 4 + 3], 1.0f);
    float v0 = d_pool[g * 4 + 0] / cnt;
    float v1 = d_pool[g * 4 + 1] / cnt;
    float v2 = d_pool[g * 4 + 2] / cnt;
    float m = fmaxf(v0, fmaxf(v1, v2));
    float l = m + logf(expf(v0 - m) + expf(v1 - m) + expf(v2 - m));
    out[g * 3 + 0] = v0 - l;
    out[g * 3 + 1] = v1 - l;
    out[g * 3 + 2] = v2 - l;
}

// ---------------- launch --------------------------------------------------------
extern "C" void kernel_launch(void* const* d_in, const int* in_sizes, int n_in,
                              void* d_out, int out_size)
{
    const float* x    = (const float*)d_in[0];
    const int*   ei   = (const int*)d_in[1];
    const int*   batch= (const int*)d_in[2];
    const float* W1   = (const float*)d_in[3];
    const float* b1   = (const float*)d_in[4];
    const float* g1   = (const float*)d_in[5];
    const float* be1  = (const float*)d_in[6];
    const float* W2   = (const float*)d_in[7];
    const float* b2   = (const float*)d_in[8];
    const float* g2   = (const float*)d_in[9];
    const float* be2  = (const float*)d_in[10];
    const float* W3   = (const float*)d_in[11];
    const float* b3   = (const float*)d_in[12];
    float* out = (float*)d_out;

    float *bufT, *bufA, *h3t, *h3, *sum1, *sq1, *sum2, *sq2;
    cudaGetSymbolAddress((void**)&bufT, d_bufT);
    cudaGetSymbolAddress((void**)&bufA, d_bufA);
    cudaGetSymbolAddress((void**)&h3t,  d_h3t);
    cudaGetSymbolAddress((void**)&h3,   d_h3);
    cudaGetSymbolAddress((void**)&sum1, d_sum1);
    cudaGetSymbolAddress((void**)&sq1,  d_sq1);
    cudaGetSymbolAddress((void**)&sum2, d_sum2);
    cudaGetSymbolAddress((void**)&sq2,  d_sq2);

    // side stream + fork/join events, created ONCE (first call is the
    // uncaptured correctness run; captured replays reuse the same handles,
    // so the captured work is identical on every call)
    static cudaStream_t s2 = 0;
    static cudaEvent_t evFork = 0, evJoin = 0;
    if (s2 == 0) {
        cudaStreamCreateWithFlags(&s2, cudaStreamNonBlocking);
        cudaEventCreateWithFlags(&evFork, cudaEventDisableTiming);
        cudaEventCreateWithFlags(&evJoin, cudaEventDisableTiming);
    }

    const int TB = 256;
    int gN = (NN + TB - 1) / TB;
    int gE = (EE + TB - 1) / TB;

    // fork: GEMM1 (x @ W1, independent of graph structure) runs on s2
    // concurrently with the structure build on the main stream
    cudaEventRecord(evFork, 0);
    cudaStreamWaitEvent(s2, evFork, 0);

    // main stream: structure build
    k_init<<<gN, TB>>>();
    k_hist<<<gE, TB>>>(ei);
    k_partial<<<NBLK, 256>>>();

    // side stream: GEMM1 (kept 4th in submission order for the ncu slot)
    k_gemm64<DIN, false><<<(NN + 63) / 64, 256, 0, s2>>>(x, W1, bufT, NN, 0, 0, 0, 0);
    cudaEventRecord(evJoin, s2);

    k_scanblock<<<1, 128>>>();
    k_scatter<<<NBLK, 256>>>();
    k_fill<<<gE, TB>>>(ei);

    // join: agg64 needs bufT (s2) + CSR (main stream)
    cudaStreamWaitEvent(0, evJoin, 0);

    // layer 1 aggregation (+bias +BN stats)
    k_agg64<<<(NN * 32 + TB - 1) / TB, TB>>>(bufT, b1, bufA, sum1, sq1);

    // layer 2: BN+ReLU fused into GEMM's A load
    k_gemm64<DH, true><<<(NN + 63) / 64, 256>>>(bufA, W2, bufT, NN, sum1, sq1, g1, be1);
    k_agg64<<<(NN * 32 + TB - 1) / TB, TB>>>(bufT, b2, bufA, sum2, sq2);

    // layer 3: BN+ReLU fused into small GEMM, then aggregation + pooling
    k_gemm3<<<gN, TB>>>(bufA, W3, h3t, sum2, sq2, g2, be2);
    k_agg3<<<gN, TB>>>(h3t, b3, h3);
    k_pool<<<gN, TB>>>(h3, batch);
    k_final<<<1, 64>>>(out);
}

// round 9
// speedup vs baseline: 1.9100x; 1.0588x over previous
#include <cuda_runtime.h>
#include <math.h>
#include <stdint.h>

#define NN 100000
#define EE 1600000
#define DIN 256
#define DH 64
#define DOUT 3
#define NG 64
#define BN_EPSF 1e-5f

#define SCAN_ELEMS 1024
#define NBLK ((NN + SCAN_ELEMS - 1) / SCAN_ELEMS)   // 98

// ---------------- scratch (device globals; no allocation allowed) -------------
__device__ int    d_deg[NN];
__device__ __align__(16) float d_dinv[NN];
__device__ int    d_rowoff[NN + 1];
__device__ int    d_fillpos[NN];
__device__ int    d_blocksum[NBLK];
__device__ int    d_blockoff[NBLK];
__device__ int    d_csrc[EE];
__device__ __align__(16) float d_bufT[(size_t)NN * DH];
__device__ __align__(16) float d_bufA[(size_t)NN * DH];
__device__ __align__(16) float d_h3t[NN * DOUT + 4];
__device__ __align__(16) float d_h3[NN * DOUT + 4];
__device__ float  d_sum1[DH], d_sq1[DH], d_sum2[DH], d_sq2[DH];
__device__ float  d_pool[NG * 4];

// ---------------- structure build ---------------------------------------------
__global__ void k_init() {
    int i = blockIdx.x * blockDim.x + threadIdx.x;
    if (i < NN) d_deg[i] = 1;
    if (i < DH) { d_sum1[i] = 0.f; d_sq1[i] = 0.f; d_sum2[i] = 0.f; d_sq2[i] = 0.f; }
    if (i < NG * 4) d_pool[i] = 0.f;
}

__global__ void k_hist(const int* __restrict__ ei) {
    int e = blockIdx.x * blockDim.x + threadIdx.x;
    if (e < EE) atomicAdd(&d_deg[ei[EE + e]], 1);
}

__global__ void k_partial() {
    int t = threadIdx.x;
    int idx = blockIdx.x * SCAN_ELEMS + t * 4;
    int s = 0;
    if (idx < NN) {
        int4 d = *(const int4*)(d_deg + idx);
        s = d.x + d.y + d.z + d.w - 4;
        float4 r;
        r.x = rsqrtf((float)d.x);
        r.y = rsqrtf((float)d.y);
        r.z = rsqrtf((float)d.z);
        r.w = rsqrtf((float)d.w);
        *(float4*)(d_dinv + idx) = r;
    }
    __shared__ int sh[8];
#pragma unroll
    for (int o = 16; o; o >>= 1) s += __shfl_down_sync(0xffffffffu, s, o);
    if ((t & 31) == 0) sh[t >> 5] = s;
    __syncthreads();
    if (t < 32) {
        int v = (t < 8) ? sh[t] : 0;
#pragma unroll
        for (int o = 4; o; o >>= 1) v += __shfl_down_sync(0xffffffffu, v, o);
        if (t == 0) d_blocksum[blockIdx.x] = v;
    }
}

__global__ void k_scanblock() {
    __shared__ int sh[128];
    int t = threadIdx.x;
    int v = (t < NBLK) ? d_blocksum[t] : 0;
    sh[t] = v;
    __syncthreads();
#pragma unroll
    for (int off = 1; off < 128; off <<= 1) {
        int a = (t >= off) ? sh[t - off] : 0;
        __syncthreads();
        sh[t] += a;
        __syncthreads();
    }
    if (t < NBLK) d_blockoff[t] = sh[t] - v;
    if (t == 127) d_rowoff[NN] = sh[127];
}

__global__ void k_scatter() {
    __shared__ int tsum[256];
    int t = threadIdx.x;
    int idx = blockIdx.x * SCAN_ELEMS + t * 4;
    int v0 = 0, v1 = 0, v2 = 0, v3 = 0;
    if (idx < NN) {
        int4 d = *(const int4*)(d_deg + idx);
        v0 = d.x - 1; v1 = d.y - 1; v2 = d.z - 1; v3 = d.w - 1;
    }
    int s = v0 + v1 + v2 + v3;
    tsum[t] = s;
    __syncthreads();
#pragma unroll
    for (int off = 1; off < 256; off <<= 1) {
        int a = (t >= off) ? tsum[t - off] : 0;
        __syncthreads();
        tsum[t] += a;
        __syncthreads();
    }
    if (idx < NN) {
        int run = d_blockoff[blockIdx.x] + tsum[t] - s;
        int4 ro = make_int4(run, run + v0, run + v0 + v1, run + v0 + v1 + v2);
        *(int4*)(d_rowoff  + idx) = ro;
        *(int4*)(d_fillpos + idx) = ro;
    }
}

__global__ void k_fill(const int* __restrict__ ei) {
    int e = blockIdx.x * blockDim.x + threadIdx.x;
    if (e >= EE) return;
    int s = ei[e];
    int d = ei[EE + e];
    int p = atomicAdd(&d_fillpos[d], 1);
    d_csrc[p] = s;
}

// ---------------- tf32 tensor-core GEMM (3xTF32 compensated) -------------------
__device__ __forceinline__ uint32_t f2tf32(float x) {
    uint32_t r;
    asm("cvt.rna.tf32.f32 %0, %1;" : "=r"(r) : "f"(x));
    return r;
}

__device__ __forceinline__ void mma_tf32(float* c, const uint32_t* a,
                                         uint32_t b0, uint32_t b1) {
    asm volatile(
        "mma.sync.aligned.m16n8k8.row.col.f32.tf32.tf32.f32 "
        "{%0,%1,%2,%3},{%4,%5,%6,%7},{%8,%9},{%0,%1,%2,%3};"
        : "+f"(c[0]), "+f"(c[1]), "+f"(c[2]), "+f"(c[3])
        : "r"(a[0]), "r"(a[1]), "r"(a[2]), "r"(a[3]), "r"(b0), "r"(b1));
}

// [nrows,K] @ [K,64] -> [nrows,64].  Block: 128 rows x 64 cols, 8 warps.
// Each warp: 16 rows x 64 cols = 8 n-subtiles of m16n8.
// BN=true: relu(a*v+b) applied to A elements during smem staging.
#define KC 32
#define SPAD 36
template <int K, bool BN>
__global__ void __launch_bounds__(256)
k_gemmTC(const float* __restrict__ A, const float* __restrict__ W,
         float* __restrict__ out, int nrows,
         const float* __restrict__ sumv, const float* __restrict__ sqv,
         const float* __restrict__ g, const float* __restrict__ be)
{
    __shared__ __align__(16) float sA[128 * SPAD];   // [row][k]
    __shared__ __align__(16) float sBt[64 * SPAD];   // [n][k]  (W transposed)
    __shared__ float bnA[64], bnB[64];

    int tid  = threadIdx.x;
    int lane = tid & 31;
    int wid  = tid >> 5;
    int lg = lane >> 2;       // group id 0..7
    int lk = lane & 3;        // 0..3
    int row0 = blockIdx.x * 128;
    int wrow = wid * 16;      // warp's row offset within tile

    if (BN) {
        if (tid < 64) {
            float mu  = sumv[tid] * (1.0f / NN);
            float var = sqv[tid] * (1.0f / NN) - mu * mu;
            float a = g[tid] * rsqrtf(var + BN_EPSF);
            bnA[tid] = a;
            bnB[tid] = be[tid] - mu * a;
        }
        __syncthreads();
    }

    float C[8][4];
#pragma unroll
    for (int n = 0; n < 8; n++)
#pragma unroll
        for (int j = 0; j < 4; j++) C[n][j] = 0.f;

    for (int kc = 0; kc < K; kc += KC) {
        // stage A chunk: 128 rows x 32 k  (1024 float4, 4 per thread)
#pragma unroll
        for (int it = 0; it < 4; it++) {
            int f4 = it * 256 + tid;
            int r  = f4 >> 3;
            int c4 = (f4 & 7) * 4;
            float4 v = make_float4(0.f, 0.f, 0.f, 0.f);
            if (row0 + r < nrows)
                v = *(const float4*)(A + (size_t)(row0 + r) * K + kc + c4);
            if (BN) {
                int c = kc + c4;
                v.x = fmaxf(fmaf(v.x, bnA[c + 0], bnB[c + 0]), 0.f);
                v.y = fmaxf(fmaf(v.y, bnA[c + 1], bnB[c + 1]), 0.f);
                v.z = fmaxf(fmaf(v.z, bnA[c + 2], bnB[c + 2]), 0.f);
                v.w = fmaxf(fmaf(v.w, bnA[c + 3], bnB[c + 3]), 0.f);
            }
            *(float4*)(sA + r * SPAD + c4) = v;
        }
        // stage W chunk transposed: sBt[n][k] = W[kc+k][n]  (512 float4, 2/thread)
#pragma unroll
        for (int it = 0; it < 2; it++) {
            int f4 = it * 256 + tid;
            int k  = f4 >> 4;
            int n4 = (f4 & 15) * 4;
            float4 v = *(const float4*)(W + (size_t)(kc + k) * 64 + n4);
            sBt[(n4 + 0) * SPAD + k] = v.x;
            sBt[(n4 + 1) * SPAD + k] = v.y;
            sBt[(n4 + 2) * SPAD + k] = v.z;
            sBt[(n4 + 3) * SPAD + k] = v.w;
        }
        __syncthreads();

#pragma unroll
        for (int kk = 0; kk < KC; kk += 8) {
            // A fragment (m16k8): rows wrow+lg, wrow+lg+8; k = kk+lk, kk+lk+4
            float af0 = sA[(wrow + lg)     * SPAD + kk + lk];
            float af1 = sA[(wrow + lg + 8) * SPAD + kk + lk];
            float af2 = sA[(wrow + lg)     * SPAD + kk + lk + 4];
            float af3 = sA[(wrow + lg + 8) * SPAD + kk + lk + 4];
            uint32_t ahi[4], alo[4];
            ahi[0] = f2tf32(af0); alo[0] = f2tf32(af0 - __uint_as_float(ahi[0]));
            ahi[1] = f2tf32(af1); alo[1] = f2tf32(af1 - __uint_as_float(ahi[1]));
            ahi[2] = f2tf32(af2); alo[2] = f2tf32(af2 - __uint_as_float(ahi[2]));
            ahi[3] = f2tf32(af3); alo[3] = f2tf32(af3 - __uint_as_float(ahi[3]));
#pragma unroll
            for (int nt = 0; nt < 8; nt++) {
                // B fragment (k8n8, col-major): k = kk+lk(+4), n = nt*8+lg
                float b0f = sBt[(nt * 8 + lg) * SPAD + kk + lk];
                float b1f = sBt[(nt * 8 + lg) * SPAD + kk + lk + 4];
                uint32_t bh0 = f2tf32(b0f), bl0 = f2tf32(b0f - __uint_as_float(bh0));
                uint32_t bh1 = f2tf32(b1f), bl1 = f2tf32(b1f - __uint_as_float(bh1));
                mma_tf32(C[nt], alo, bh0, bh1);
                mma_tf32(C[nt], ahi, bl0, bl1);
                mma_tf32(C[nt], ahi, bh0, bh1);
            }
        }
        __syncthreads();
    }

    // epilogue: c0,c1 -> (row, 2*lk, 2*lk+1); c2,c3 -> (row+8, ...)
    int r0 = row0 + wrow + lg;
    int r1 = r0 + 8;
#pragma unroll
    for (int nt = 0; nt < 8; nt++) {
        int col = nt * 8 + 2 * lk;
        if (r0 < nrows)
            *(float2*)(out + (size_t)r0 * 64 + col) = make_float2(C[nt][0], C[nt][1]);
        if (r1 < nrows)
            *(float2*)(out + (size_t)r1 * 64 + col) = make_float2(C[nt][2], C[nt][3]);
    }
}

// ---------------- aggregation (pull, CSR by dst) + bias + fused BN stats -------
__global__ void k_agg64(const float* __restrict__ ht, const float* __restrict__ bias,
                        float* __restrict__ out,
                        float* __restrict__ sumv, float* __restrict__ sqv)
{
    __shared__ float s_s[8 * 64];
    __shared__ float s_q[8 * 64];
    int warp = (blockIdx.x * blockDim.x + threadIdx.x) >> 5;
    int w    = threadIdx.x >> 5;
    int lane = threadIdx.x & 31;
    int c0   = lane * 2;
    float acc0 = 0.f, acc1 = 0.f;
    if (warp < NN) {
        const int i = warp;
        float di = d_dinv[i];
        float2 sv = *(const float2*)(ht + i * 64 + c0);
        acc0 = di * di * sv.x;
        acc1 = di * di * sv.y;
        int e0 = d_rowoff[i], e1 = d_rowoff[i + 1];
        for (int j0 = e0; j0 < e1; j0 += 32) {
            int j = j0 + lane;
            int src = 0; float dv = 0.f;
            if (j < e1) { src = d_csrc[j]; dv = __ldg(&d_dinv[src]); }
            int cnt = min(32, e1 - j0);
#pragma unroll 4
            for (int k = 0; k < cnt; k++) {
                int   sk = __shfl_sync(0xffffffffu, src, k);
                float wk = __shfl_sync(0xffffffffu, dv, k) * di;
                float2 hv = __ldg((const float2*)(ht + sk * 64 + c0));
                acc0 = fmaf(wk, hv.x, acc0);
                acc1 = fmaf(wk, hv.y, acc1);
            }
        }
        acc0 += bias[c0];
        acc1 += bias[c0 + 1];
        *(float2*)(out + i * 64 + c0) = make_float2(acc0, acc1);
    }
    s_s[w * 64 + c0]     = acc0;
    s_s[w * 64 + c0 + 1] = acc1;
    s_q[w * 64 + c0]     = acc0 * acc0;
    s_q[w * 64 + c0 + 1] = acc1 * acc1;
    __syncthreads();
    if (threadIdx.x < 64) {
        float ss = 0.f, qs = 0.f;
#pragma unroll
        for (int r = 0; r < 8; r++) {
            ss += s_s[r * 64 + threadIdx.x];
            qs += s_q[r * 64 + threadIdx.x];
        }
        atomicAdd(&sumv[threadIdx.x], ss);
        atomicAdd(&sqv[threadIdx.x], qs);
    }
}

// ---------------- layer 3: BN+ReLU inline, [N,64]@[64,3] -----------------------
__global__ void k_gemm3(const float* __restrict__ h, const float* __restrict__ W3,
                        float* __restrict__ out,
                        const float* __restrict__ sumv, const float* __restrict__ sqv,
                        const float* __restrict__ g, const float* __restrict__ be)
{
    __shared__ float wsh[DH * DOUT];
    __shared__ float bnA[64], bnB[64];
    if (threadIdx.x < DH * DOUT) wsh[threadIdx.x] = W3[threadIdx.x];
    if (threadIdx.x < 64) {
        float mu  = sumv[threadIdx.x] * (1.0f / NN);
        float var = sqv[threadIdx.x] * (1.0f / NN) - mu * mu;
        float a = g[threadIdx.x] * rsqrtf(var + BN_EPSF);
        bnA[threadIdx.x] = a;
        bnB[threadIdx.x] = be[threadIdx.x] - mu * a;
    }
    __syncthreads();
    int i = blockIdx.x * blockDim.x + threadIdx.x;
    if (i >= NN) return;
    float a0 = 0.f, a1 = 0.f, a2 = 0.f;
    const float4* hp = (const float4*)(h + (size_t)i * DH);
#pragma unroll
    for (int q4 = 0; q4 < 16; q4++) {
        float4 v = hp[q4];
        int k = q4 * 4;
        float e0 = fmaxf(fmaf(v.x, bnA[k + 0], bnB[k + 0]), 0.f);
        float e1 = fmaxf(fmaf(v.y, bnA[k + 1], bnB[k + 1]), 0.f);
        float e2 = fmaxf(fmaf(v.z, bnA[k + 2], bnB[k + 2]), 0.f);
        float e3 = fmaxf(fmaf(v.w, bnA[k + 3], bnB[k + 3]), 0.f);
        a0 = fmaf(e0, wsh[(k + 0) * 3 + 0], a0); a1 = fmaf(e0, wsh[(k + 0) * 3 + 1], a1); a2 = fmaf(e0, wsh[(k + 0) * 3 + 2], a2);
        a0 = fmaf(e1, wsh[(k + 1) * 3 + 0], a0); a1 = fmaf(e1, wsh[(k + 1) * 3 + 1], a1); a2 = fmaf(e1, wsh[(k + 1) * 3 + 2], a2);
        a0 = fmaf(e2, wsh[(k + 2) * 3 + 0], a0); a1 = fmaf(e2, wsh[(k + 2) * 3 + 1], a1); a2 = fmaf(e2, wsh[(k + 2) * 3 + 2], a2);
        a0 = fmaf(e3, wsh[(k + 3) * 3 + 0], a0); a1 = fmaf(e3, wsh[(k + 3) * 3 + 1], a1); a2 = fmaf(e3, wsh[(k + 3) * 3 + 2], a2);
    }
    out[i * 3 + 0] = a0; out[i * 3 + 1] = a1; out[i * 3 + 2] = a2;
}

__global__ void k_agg3(const float* __restrict__ ht, const float* __restrict__ b3,
                       float* __restrict__ out)
{
    int i = blockIdx.x * blockDim.x + threadIdx.x;
    if (i >= NN) return;
    float di = d_dinv[i], ws = di * di;
    float a0 = ws * ht[i * 3 + 0];
    float a1 = ws * ht[i * 3 + 1];
    float a2 = ws * ht[i * 3 + 2];
    int e1 = d_rowoff[i + 1];
    for (int j = d_rowoff[i]; j < e1; j++) {
        int s = d_csrc[j];
        float w = __ldg(&d_dinv[s]) * di;
        a0 = fmaf(w, ht[s * 3 + 0], a0);
        a1 = fmaf(w, ht[s * 3 + 1], a1);
        a2 = fmaf(w, ht[s * 3 + 2], a2);
    }
    out[i * 3 + 0] = a0 + b3[0];
    out[i * 3 + 1] = a1 + b3[1];
    out[i * 3 + 2] = a2 + b3[2];
}

// ---------------- pooling + log_softmax ----------------------------------------
__global__ void k_pool(const float* __restrict__ h3, const int* __restrict__ batch)
{
    __shared__ float sh[NG * 4];
    if (threadIdx.x < NG * 4) sh[threadIdx.x] = 0.f;
    __syncthreads();
    int i = blockIdx.x * blockDim.x + threadIdx.x;
    if (i < NN) {
        int g = batch[i];
        atomicAdd(&sh[g * 4 + 0], h3[i * 3 + 0]);
        atomicAdd(&sh[g * 4 + 1], h3[i * 3 + 1]);
        atomicAdd(&sh[g * 4 + 2], h3[i * 3 + 2]);
        atomicAdd(&sh[g * 4 + 3], 1.0f);
    }
    __syncthreads();
    if (threadIdx.x < NG * 4 && sh[threadIdx.x] != 0.f)
        atomicAdd(&d_pool[threadIdx.x], sh[threadIdx.x]);
}

__global__ void k_final(float* __restrict__ out)
{
    int g = threadIdx.x;
    if (g >= NG) return;
    float cnt = fmaxf(d_pool[g * 4 + 3], 1.0f);
    float v0 = d_pool[g * 4 + 0] / cnt;
    float v1 = d_pool[g * 4 + 1] / cnt;
    float v2 = d_pool[g * 4 + 2] / cnt;
    float m = fmaxf(v0, fmaxf(v1, v2));
    float l = m + logf(expf(v0 - m) + expf(v1 - m) + expf(v2 - m));
    out[g * 3 + 0] = v0 - l;
    out[g * 3 + 1] = v1 - l;
    out[g * 3 + 2] = v2 - l;
}

// ---------------- launch --------------------------------------------------------
extern "C" void kernel_launch(void* const* d_in, const int* in_sizes, int n_in,
                              void* d_out, int out_size)
{
    const float* x    = (const float*)d_in[0];
    const int*   ei   = (const int*)d_in[1];
    const int*   batch= (const int*)d_in[2];
    const float* W1   = (const float*)d_in[3];
    const float* b1   = (const float*)d_in[4];
    const float* g1   = (const float*)d_in[5];
    const float* be1  = (const float*)d_in[6];
    const float* W2   = (const float*)d_in[7];
    const float* b2   = (const float*)d_in[8];
    const float* g2   = (const float*)d_in[9];
    const float* be2  = (const float*)d_in[10];
    const float* W3   = (const float*)d_in[11];
    const float* b3   = (const float*)d_in[12];
    float* out = (float*)d_out;

    float *bufT, *bufA, *h3t, *h3, *sum1, *sq1, *sum2, *sq2;
    cudaGetSymbolAddress((void**)&bufT, d_bufT);
    cudaGetSymbolAddress((void**)&bufA, d_bufA);
    cudaGetSymbolAddress((void**)&h3t,  d_h3t);
    cudaGetSymbolAddress((void**)&h3,   d_h3);
    cudaGetSymbolAddress((void**)&sum1, d_sum1);
    cudaGetSymbolAddress((void**)&sq1,  d_sq1);
    cudaGetSymbolAddress((void**)&sum2, d_sum2);
    cudaGetSymbolAddress((void**)&sq2,  d_sq2);

    static cudaStream_t s2 = 0;
    static cudaEvent_t evFork = 0, evJoin = 0;
    if (s2 == 0) {
        cudaStreamCreateWithFlags(&s2, cudaStreamNonBlocking);
        cudaEventCreateWithFlags(&evFork, cudaEventDisableTiming);
        cudaEventCreateWithFlags(&evJoin, cudaEventDisableTiming);
    }

    const int TB = 256;
    int gN = (NN + TB - 1) / TB;
    int gE = (EE + TB - 1) / TB;
    int gTC = (NN + 127) / 128;

    // fork: GEMM1 on side stream, overlapped with structure build
    cudaEventRecord(evFork, 0);
    cudaStreamWaitEvent(s2, evFork, 0);

    k_init<<<gN, TB>>>();
    k_hist<<<gE, TB>>>(ei);
    k_partial<<<NBLK, 256>>>();

    // side stream: tensor-core GEMM1 (slot 4 for the ncu capture)
    k_gemmTC<DIN, false><<<gTC, 256, 0, s2>>>(x, W1, bufT, NN, 0, 0, 0, 0);
    cudaEventRecord(evJoin, s2);

    k_scanblock<<<1, 128>>>();
    k_scatter<<<NBLK, 256>>>();
    k_fill<<<gE, TB>>>(ei);

    cudaStreamWaitEvent(0, evJoin, 0);

    // layer 1 aggregation (+bias +BN stats)
    k_agg64<<<(NN * 32 + TB - 1) / TB, TB>>>(bufT, b1, bufA, sum1, sq1);

    // layer 2: tensor-core GEMM with BN+ReLU fused into A staging
    k_gemmTC<DH, true><<<gTC, 256>>>(bufA, W2, bufT, NN, sum1, sq1, g1, be1);
    k_agg64<<<(NN * 32 + TB - 1) / TB, TB>>>(bufT, b2, bufA, sum2, sq2);

    // layer 3
    k_gemm3<<<gN, TB>>>(bufA, W3, h3t, sum2, sq2, g2, be2);
    k_agg3<<<gN, TB>>>(h3t, b3, h3);
    k_pool<<<gN, TB>>>(h3, batch);
    k_final<<<1, 64>>>(out);
}